// round 12
// baseline (speedup 1.0000x reference)
#include <cuda_runtime.h>
#include <math.h>

#define B_SZ 2048
#define T_SZ 200
#define NB   16

typedef unsigned long long u64;

// ---- packed fp32x2 helpers (SASS FFMA2: only reachable via PTX) ----
__device__ __forceinline__ void ffma2(u64 &d, u64 a, u64 b){
    asm("fma.rn.f32x2 %0, %1, %2, %0;" : "+l"(d) : "l"(a), "l"(b));
}
__device__ __forceinline__ u64 pack2(float lo, float hi){
    u64 r; asm("mov.b64 %0, {%1, %2};" : "=l"(r) : "f"(lo), "f"(hi)); return r;
}
__device__ __forceinline__ float2 unpack2(u64 v){
    float2 r; asm("mov.b64 {%0, %1}, %2;" : "=f"(r.x), "=f"(r.y) : "l"(v)); return r;
}

// ---- fast activations: MUFU-based, rel err ~1e-6 ----
__device__ __forceinline__ float fex2(float x){ float r; asm("ex2.approx.f32 %0, %1;" : "=f"(r) : "f"(x)); return r; }
__device__ __forceinline__ float frcp(float x){ float r; asm("rcp.approx.f32 %0, %1;" : "=f"(r) : "f"(x)); return r; }
#define LOG2E 1.4426950408889634f
__device__ __forceinline__ float sigf(float x){
    return frcp(1.0f + fex2(-LOG2E*x));
}
__device__ __forceinline__ float tanhfast(float x){
    float t = fminf(2.0f*LOG2E*x, 126.0f);
    float e = fex2(t);
    return (e - 1.0f) * frcp(e + 1.0f);
}

// ---------------- device scratch ----------------
__device__ __align__(16) float g_l1_whhT[2][128*512];
__device__ __align__(16) float g_l1_wih [2][512];
__device__ __align__(16) float g_l1_b   [2][512];
__device__ __align__(16) float g_l2_wihT[2][256*512];
__device__ __align__(16) float g_l2_whhT[2][128*512];
__device__ __align__(16) float g_l2_b   [2][512];
__device__ __align__(16) float g_fc1_wT[256*256];
__device__ __align__(16) float g_fc2_wT[256*64];
__device__ __align__(16) float g_g1_whhT[128*512];
__device__ __align__(16) float g_g1_wih[512];
__device__ __align__(16) float g_g1_bih[512];
__device__ __align__(16) float g_g1_bhh[512];
__device__ __align__(16) float g_g2_wihT[128*160];
__device__ __align__(16) float g_g2_whhT[50*160];
__device__ __align__(16) float g_h1out[(size_t)T_SZ*B_SZ*256];  // [t][b][256]
__device__ __align__(16) float g_hn[4][B_SZ*128];
__device__ __align__(16) float g_hidden[B_SZ*128];

// ---------------- weight permutation (gate-quad layout: col = h*4+q) ----------------
__global__ void k_prep(
    const float* __restrict__ l1_wih_f, const float* __restrict__ l1_whh_f, const float* __restrict__ l1_b_f,
    const float* __restrict__ l1_wih_b, const float* __restrict__ l1_whh_b, const float* __restrict__ l1_b_b,
    const float* __restrict__ l2_wih_f, const float* __restrict__ l2_whh_f, const float* __restrict__ l2_b_f,
    const float* __restrict__ l2_wih_b, const float* __restrict__ l2_whh_b, const float* __restrict__ l2_b_b,
    const float* __restrict__ fc1_w, const float* __restrict__ fc2_w,
    const float* __restrict__ g1_wih, const float* __restrict__ g1_whh,
    const float* __restrict__ g1_bih, const float* __restrict__ g1_bhh,
    const float* __restrict__ g2_wih, const float* __restrict__ g2_whh)
{
    const int idx = blockIdx.x*blockDim.x + threadIdx.x;
    const int stride = gridDim.x*blockDim.x;

    for (int i=idx; i<2*128*512; i+=stride){
        int dir=i>>16, r=i&65535, k=r>>9, col=r&511, h=col>>2, q=col&3;
        const float* s = dir ? l1_whh_b : l1_whh_f;
        g_l1_whhT[dir][r] = s[(q*128+h)*128 + k];
    }
    for (int i=idx; i<2*128*512; i+=stride){
        int dir=i>>16, r=i&65535, k=r>>9, col=r&511, h=col>>2, q=col&3;
        const float* s = dir ? l2_whh_b : l2_whh_f;
        g_l2_whhT[dir][r] = s[(q*128+h)*128 + k];
    }
    for (int i=idx; i<2*256*512; i+=stride){
        int dir=i>>17, r=i&131071, k=r>>9, col=r&511, h=col>>2, q=col&3;
        const float* s = dir ? l2_wih_b : l2_wih_f;
        g_l2_wihT[dir][r] = s[(q*128+h)*256 + k];
    }
    for (int i=idx; i<2*512; i+=stride){
        int dir=i>>9, col=i&511, h=col>>2, q=col&3, g=q*128+h;
        g_l1_wih[dir][col] = (dir ? l1_wih_b : l1_wih_f)[g];
        g_l1_b  [dir][col] = (dir ? l1_b_b   : l1_b_f  )[g];
        g_l2_b  [dir][col] = (dir ? l2_b_b   : l2_b_f  )[g];
    }
    for (int i=idx; i<256*256; i+=stride){
        int c=i>>8, j=i&255;
        g_fc1_wT[i] = fc1_w[j*256+c];
    }
    for (int i=idx; i<256*64; i+=stride){
        int c=i>>6, j=i&63;
        g_fc2_wT[i] = fc2_w[j*256+c];
    }
    for (int i=idx; i<128*512; i+=stride){
        int k=i>>9, col=i&511, h=col>>2, q=col&3;
        g_g1_whhT[i] = (q<3) ? g1_whh[(q*128+h)*128 + k] : 0.0f;
    }
    for (int i=idx; i<512; i+=stride){
        int h=i>>2, q=i&3;
        g_g1_wih[i] = (q<3) ? g1_wih[q*128+h] : 0.0f;
        g_g1_bih[i] = (q<3) ? g1_bih[q*128+h] : 0.0f;
        g_g1_bhh[i] = (q<3) ? g1_bhh[q*128+h] : 0.0f;
    }
    for (int i=idx; i<128*160; i+=stride){
        int k=i/160, g=i%160;
        g_g2_wihT[i] = (g<150) ? g2_wih[g*128+k] : 0.0f;
    }
    for (int i=idx; i<50*160; i+=stride){
        int k=i/160, g=i%160;
        g_g2_whhT[i] = (g<150) ? g2_whh[g*50+k] : 0.0f;
    }
}

// ---------------- BiLSTM layer 1: 256 threads, thread = (hidden h, batch half) ----------------
__global__ void __launch_bounds__(256) k_lstm1(const float* __restrict__ edge)
{
    const int dir = blockIdx.y;
    const int b0  = blockIdx.x * NB;
    const int tid = threadIdx.x;
    const int hh  = tid & 127;
    const int bb0 = (tid >> 7) * 8;      // batch-half base (0 or 8)

    __shared__ float sh_x[NB][T_SZ];     // 12.8KB
    __shared__ u64   sh_hT[128][18];     // 18.4KB, stride 9x16B -> conflict-free

    for (int i = tid; i < NB*T_SZ; i += 256){
        int b = i / T_SZ, t = i % T_SZ;
        sh_x[b][t] = edge[(b0+b)*T_SZ + t];
    }
    #pragma unroll
    for (int j=0;j<8;j++) sh_hT[hh][bb0+j] = 0ull;
    float c[8];
    #pragma unroll
    for (int j=0;j<8;j++) c[j] = 0.0f;
    float hb[8];

    const ulonglong2* __restrict__ W = (const ulonglong2*)g_l1_whhT[dir];
    const u64* wib = (const u64*)g_l1_wih[dir];
    const u64* bbp = (const u64*)g_l1_b[dir];
    const u64 wi01 = wib[2*hh], wi23 = wib[2*hh+1];
    const u64 b01  = bbp[2*hh], b23  = bbp[2*hh+1];
    __syncthreads();

    for (int s=0; s<T_SZ; s++){
        const int t = dir ? (T_SZ-1-s) : s;
        u64 a01[8], a23[8];
        #pragma unroll
        for (int j=0;j<8;j++){
            float xv = sh_x[bb0+j][t];
            u64 x2 = pack2(xv, xv);
            a01[j] = b01; ffma2(a01[j], wi01, x2);
            a23[j] = b23; ffma2(a23[j], wi23, x2);
        }
        #pragma unroll 4
        for (int k=0;k<128;k++){
            ulonglong2 w = W[k*128 + hh];
            const ulonglong2* hrow = (const ulonglong2*)&sh_hT[k][bb0];
            #pragma unroll
            for (int j2=0;j2<4;j2++){
                ulonglong2 hp = hrow[j2];
                ffma2(a01[2*j2],   w.x, hp.x);
                ffma2(a23[2*j2],   w.y, hp.x);
                ffma2(a01[2*j2+1], w.x, hp.y);
                ffma2(a23[2*j2+1], w.y, hp.y);
            }
        }
        __syncthreads();
        float* outp = g_h1out + (size_t)t*(B_SZ*256) + (size_t)(b0+bb0)*256 + dir*128 + hh;
        #pragma unroll
        for (int j=0;j<8;j++){
            float2 g01 = unpack2(a01[j]);
            float2 g23 = unpack2(a23[j]);
            float ig = sigf(g01.x);
            float fg = sigf(g01.y);
            float gg = tanhfast(g23.x);
            float og = sigf(g23.y);
            c[j] = fmaf(fg, c[j], ig*gg);
            hb[j] = og * tanhfast(c[j]);
            outp[j*256] = hb[j];
        }
        ulonglong2* myrow = (ulonglong2*)&sh_hT[hh][bb0];
        #pragma unroll
        for (int j2=0;j2<4;j2++)
            myrow[j2] = make_ulonglong2(pack2(hb[2*j2],hb[2*j2]), pack2(hb[2*j2+1],hb[2*j2+1]));
        __syncthreads();
    }
    #pragma unroll
    for (int j=0;j<8;j++) g_hn[dir][(b0+bb0+j)*128 + hh] = hb[j];
}

// ---------------- BiLSTM layer 2: 256 threads, fused 256-wide projection ----------------
__global__ void __launch_bounds__(256) k_lstm2()
{
    const int dir = blockIdx.y;
    const int b0  = blockIdx.x * NB;
    const int tid = threadIdx.x;
    const int hh  = tid & 127;
    const int bb0 = (tid >> 7) * 8;

    __shared__ float sh_x[NB][256];      // plain, 16KB
    __shared__ u64   sh_hT[128][18];     // 18.4KB

    #pragma unroll
    for (int j=0;j<8;j++) sh_hT[hh][bb0+j] = 0ull;
    float c[8];
    #pragma unroll
    for (int j=0;j<8;j++) c[j] = 0.0f;
    float hb[8];

    const ulonglong2* __restrict__ Wx = (const ulonglong2*)g_l2_wihT[dir];
    const ulonglong2* __restrict__ Wh = (const ulonglong2*)g_l2_whhT[dir];
    const u64* bbp = (const u64*)g_l2_b[dir];
    const u64 b01 = bbp[2*hh], b23 = bbp[2*hh+1];
    __syncthreads();

    for (int s=0; s<T_SZ; s++){
        const int t = dir ? (T_SZ-1-s) : s;

        // fill sh_x (prev-step readers finished at the trailing sync)
        const float4* __restrict__ src =
            (const float4*)(g_h1out + (size_t)t*(B_SZ*256) + (size_t)b0*256);
        #pragma unroll
        for (int i=0;i<4;i++) ((float4*)sh_x)[tid + i*256] = src[tid + i*256];
        __syncthreads();

        u64 a01[8], a23[8];
        #pragma unroll
        for (int j=0;j<8;j++){ a01[j] = b01; a23[j] = b23; }

        #pragma unroll 4
        for (int k=0;k<256;k++){
            ulonglong2 w = Wx[k*128 + hh];
            #pragma unroll
            for (int j=0;j<8;j++){
                float xv = sh_x[bb0+j][k];
                u64 x2 = pack2(xv, xv);
                ffma2(a01[j], w.x, x2);
                ffma2(a23[j], w.y, x2);
            }
        }
        #pragma unroll 4
        for (int k=0;k<128;k++){
            ulonglong2 w = Wh[k*128 + hh];
            const ulonglong2* hrow = (const ulonglong2*)&sh_hT[k][bb0];
            #pragma unroll
            for (int j2=0;j2<4;j2++){
                ulonglong2 hp = hrow[j2];
                ffma2(a01[2*j2],   w.x, hp.x);
                ffma2(a23[2*j2],   w.y, hp.x);
                ffma2(a01[2*j2+1], w.x, hp.y);
                ffma2(a23[2*j2+1], w.y, hp.y);
            }
        }
        __syncthreads();
        #pragma unroll
        for (int j=0;j<8;j++){
            float2 g01 = unpack2(a01[j]);
            float2 g23 = unpack2(a23[j]);
            float ig = sigf(g01.x);
            float fg = sigf(g01.y);
            float gg = tanhfast(g23.x);
            float og = sigf(g23.y);
            c[j] = fmaf(fg, c[j], ig*gg);
            hb[j] = og * tanhfast(c[j]);
        }
        ulonglong2* myrow = (ulonglong2*)&sh_hT[hh][bb0];
        #pragma unroll
        for (int j2=0;j2<4;j2++)
            myrow[j2] = make_ulonglong2(pack2(hb[2*j2],hb[2*j2]), pack2(hb[2*j2+1],hb[2*j2+1]));
        __syncthreads();    // h writes visible; sh_x safe to refill
    }
    #pragma unroll
    for (int j=0;j<8;j++) g_hn[2+dir][(b0+bb0+j)*128 + hh] = hb[j];
}

// ---------------- FC head ----------------
__global__ void __launch_bounds__(256) k_fc(const int* __restrict__ node_data,
                                            const float* __restrict__ emb,
                                            const float* __restrict__ fc1_b,
                                            const float* __restrict__ fc2_b)
{
    const int r = blockIdx.x;
    const int c = threadIdx.x;
    __shared__ float sh_in[256];
    __shared__ float sh_mid[256];

    int d = r >> 10;
    int b = ((r & 1023) << 1) + (c >> 7);
    int k = c & 127;
    sh_in[c] = g_hn[d][b*128 + k] + g_hn[2+d][b*128 + k];
    __syncthreads();

    float acc = fc1_b[c];
    #pragma unroll 4
    for (int i=0;i<256;i++) acc = fmaf(sh_in[i], g_fc1_wT[i*256 + c], acc);
    sh_mid[c] = sigf(acc);
    __syncthreads();

    if (c < 64){
        float a2 = fc2_b[c];
        #pragma unroll 4
        for (int i=0;i<256;i++) a2 = fmaf(sh_mid[i], g_fc2_wT[i*64 + c], a2);
        g_hidden[r*128 + c] = sigf(a2);
    } else if (c < 128){
        int e = c - 64;
        int n0 = node_data[r*2], n1 = node_data[r*2+1];
        g_hidden[r*128 + 64 + e] = 0.5f*(emb[n0*64 + e] + emb[n1*64 + e]);
    }
}

// ---------------- decoder: GRU(128) -> GRU(50) -> sigmoid, 200 steps ----------------
__global__ void __launch_bounds__(160) k_dec(const float* __restrict__ edge,
                                             const float* __restrict__ g2_bih,
                                             const float* __restrict__ g2_bhh,
                                             const float* __restrict__ dec_w,
                                             const float* __restrict__ dec_b,
                                             float* __restrict__ out)
{
    const int b0  = blockIdx.x * NB;
    const int tid = threadIdx.x;     // 0..159

    __shared__ u64   h1dT[128][18];
    __shared__ u64   h1p[128][9];
    __shared__ u64   h2p[52][9];
    __shared__ float h2s[NB][52];
    __shared__ float s_rz[NB][100];
    __shared__ float s_in[NB][52];
    __shared__ float s_hn[NB][52];
    __shared__ float res[NB];
    __shared__ float dw[52];

    if (tid < 128){
        float v[NB];
        #pragma unroll
        for (int b=0;b<NB;b++) v[b] = g_hidden[(b0+b)*128 + tid];
        ulonglong2* myrow = (ulonglong2*)h1dT[tid];
        #pragma unroll
        for (int j=0;j<8;j++)
            myrow[j] = make_ulonglong2(pack2(v[2*j],v[2*j]), pack2(v[2*j+1],v[2*j+1]));
        #pragma unroll
        for (int bp=0;bp<8;bp++) h1p[tid][bp] = pack2(v[2*bp], v[2*bp+1]);
    }
    if (tid < 52){
        #pragma unroll
        for (int b=0;b<NB;b++) h2s[b][tid] = 0.0f;
        #pragma unroll
        for (int bp=0;bp<8;bp++) h2p[tid][bp] = 0ull;
        dw[tid] = (tid < 50) ? dec_w[tid] : 0.0f;
    }
    if (tid < NB) res[tid] = edge[(b0+tid)*T_SZ + (T_SZ-1)];

    float4 wi = {0,0,0,0}, bi = {0,0,0,0}, bh = {0,0,0,0};
    if (tid < 128){
        wi = ((const float4*)g_g1_wih)[tid];
        bi = ((const float4*)g_g1_bih)[tid];
        bh = ((const float4*)g_g1_bhh)[tid];
    }
    float g2bi = 0.0f, g2bh = 0.0f;
    if (tid < 150){ g2bi = g2_bih[tid]; g2bh = g2_bhh[tid]; }
    const float decb = dec_b[0];
    __syncthreads();

    for (int t=0; t<T_SZ; t++){
        u64 a01[NB], a23[NB];
        if (tid < 128){
            const u64 bh01 = pack2(bh.x, bh.y);
            const u64 bh23 = pack2(bh.z, bh.w);
            #pragma unroll
            for (int b=0;b<NB;b++){ a01[b] = bh01; a23[b] = bh23; }
            const ulonglong2* __restrict__ W = (const ulonglong2*)g_g1_whhT;
            #pragma unroll 4
            for (int k=0;k<128;k++){
                ulonglong2 w = W[k*128 + tid];
                const ulonglong2* hrow = (const ulonglong2*)h1dT[k];
                #pragma unroll
                for (int j=0;j<8;j++){
                    ulonglong2 hp = hrow[j];
                    ffma2(a01[2*j],   w.x, hp.x);
                    ffma2(a23[2*j],   w.y, hp.x);
                    ffma2(a01[2*j+1], w.x, hp.y);
                    ffma2(a23[2*j+1], w.y, hp.y);
                }
            }
        }
        __syncthreads();

        if (tid < 128){
            float hn_[NB];
            #pragma unroll
            for (int b=0;b<NB;b++){
                float2 g01 = unpack2(a01[b]);
                float2 g23 = unpack2(a23[b]);
                float rv  = res[b];
                float ir  = fmaf(rv, wi.x, bi.x);
                float iz  = fmaf(rv, wi.y, bi.y);
                float inn = fmaf(rv, wi.z, bi.z);
                float rg = sigf(ir + g01.x);
                float zg = sigf(iz + g01.y);
                float ng = tanhfast(fmaf(rg, g23.x, inn));
                float h1 = unpack2(h1dT[tid][b]).x;
                hn_[b] = fmaf(zg, h1 - ng, ng);
            }
            ulonglong2* myrow = (ulonglong2*)h1dT[tid];
            #pragma unroll
            for (int j=0;j<8;j++)
                myrow[j] = make_ulonglong2(pack2(hn_[2*j],hn_[2*j]), pack2(hn_[2*j+1],hn_[2*j+1]));
            #pragma unroll
            for (int bp=0;bp<8;bp++) h1p[tid][bp] = pack2(hn_[2*bp], hn_[2*bp+1]);
        }
        __syncthreads();

        if (tid < 150){
            u64 gi2[8], gh2[8];
            const u64 bi2 = pack2(g2bi, g2bi);
            const u64 bh2 = pack2(g2bh, g2bh);
            #pragma unroll
            for (int bp=0;bp<8;bp++){ gi2[bp] = bi2; gh2[bp] = bh2; }
            #pragma unroll 4
            for (int k=0;k<128;k++){
                float w = g_g2_wihT[k*160 + tid];
                u64 w2 = pack2(w, w);
                #pragma unroll
                for (int bp=0;bp<8;bp++) ffma2(gi2[bp], h1p[k][bp], w2);
            }
            #pragma unroll 2
            for (int k=0;k<50;k++){
                float w = g_g2_whhT[k*160 + tid];
                u64 w2 = pack2(w, w);
                #pragma unroll
                for (int bp=0;bp<8;bp++) ffma2(gh2[bp], h2p[k][bp], w2);
            }
            if (tid < 100){
                #pragma unroll
                for (int bp=0;bp<8;bp++){
                    float2 a = unpack2(gi2[bp]);
                    float2 b = unpack2(gh2[bp]);
                    s_rz[2*bp][tid]   = a.x + b.x;
                    s_rz[2*bp+1][tid] = a.y + b.y;
                }
            } else {
                int n = tid - 100;
                #pragma unroll
                for (int bp=0;bp<8;bp++){
                    float2 a = unpack2(gi2[bp]);
                    float2 b = unpack2(gh2[bp]);
                    s_in[2*bp][n]   = a.x;  s_hn[2*bp][n]   = b.x;
                    s_in[2*bp+1][n] = a.y;  s_hn[2*bp+1][n] = b.y;
                }
            }
        }
        __syncthreads();

        if (tid < 50){
            float h2n[NB];
            #pragma unroll
            for (int b=0;b<NB;b++){
                float rg = sigf(s_rz[b][tid]);
                float zg = sigf(s_rz[b][50+tid]);
                float ng = tanhfast(fmaf(rg, s_hn[b][tid], s_in[b][tid]));
                float h2 = h2s[b][tid];
                h2n[b] = fmaf(zg, h2 - ng, ng);
                h2s[b][tid] = h2n[b];
            }
            #pragma unroll
            for (int bp=0;bp<8;bp++) h2p[tid][bp] = pack2(h2n[2*bp], h2n[2*bp+1]);
        }
        __syncthreads();

        if (tid < NB){
            float s = decb;
            #pragma unroll 2
            for (int k=0;k<50;k++) s = fmaf(h2s[tid][k], dw[k], s);
            float r = sigf(s);
            res[tid] = r;
            out[(b0+tid)*T_SZ + t] = r;
        }
        __syncthreads();
    }
}

extern "C" void kernel_launch(void* const* d_in, const int* in_sizes, int n_in,
                              void* d_out, int out_size)
{
    const int*   node_data = (const int*)  d_in[0];
    const float* edge_data = (const float*)d_in[1];
    const float* emb       = (const float*)d_in[2];
    const float* l1_wih_f  = (const float*)d_in[3];
    const float* l1_whh_f  = (const float*)d_in[4];
    const float* l1_b_f    = (const float*)d_in[5];
    const float* l1_wih_b  = (const float*)d_in[6];
    const float* l1_whh_b  = (const float*)d_in[7];
    const float* l1_b_b    = (const float*)d_in[8];
    const float* l2_wih_f  = (const float*)d_in[9];
    const float* l2_whh_f  = (const float*)d_in[10];
    const float* l2_b_f    = (const float*)d_in[11];
    const float* l2_wih_b  = (const float*)d_in[12];
    const float* l2_whh_b  = (const float*)d_in[13];
    const float* l2_b_b    = (const float*)d_in[14];
    const float* fc1_w     = (const float*)d_in[15];
    const float* fc1_b     = (const float*)d_in[16];
    const float* fc2_w     = (const float*)d_in[17];
    const float* fc2_b     = (const float*)d_in[18];
    const float* g1_wih    = (const float*)d_in[19];
    const float* g1_whh    = (const float*)d_in[20];
    const float* g1_bih    = (const float*)d_in[21];
    const float* g1_bhh    = (const float*)d_in[22];
    const float* g2_wih    = (const float*)d_in[23];
    const float* g2_whh    = (const float*)d_in[24];
    const float* g2_bih    = (const float*)d_in[25];
    const float* g2_bhh    = (const float*)d_in[26];
    const float* dec_w     = (const float*)d_in[27];
    const float* dec_b     = (const float*)d_in[28];
    float* out = (float*)d_out;

    k_prep<<<256, 256>>>(l1_wih_f, l1_whh_f, l1_b_f, l1_wih_b, l1_whh_b, l1_b_b,
                         l2_wih_f, l2_whh_f, l2_b_f, l2_wih_b, l2_whh_b, l2_b_b,
                         fc1_w, fc2_w, g1_wih, g1_whh, g1_bih, g1_bhh,
                         g2_wih, g2_whh);
    k_lstm1<<<dim3(B_SZ/NB, 2), 256>>>(edge_data);
    k_lstm2<<<dim3(B_SZ/NB, 2), 256>>>();
    k_fc<<<B_SZ, 256>>>(node_data, emb, fc1_b, fc2_b);
    k_dec<<<B_SZ/NB, 160>>>(edge_data, g2_bih, g2_bhh, dec_w, dec_b, out);
}

// round 13
// speedup vs baseline: 1.2880x; 1.2880x over previous
#include <cuda_runtime.h>
#include <math.h>
#include <stdint.h>

#define B_SZ 2048
#define T_SZ 200
#define NB   16

typedef unsigned long long u64;

// ---- packed fp32x2 helpers (SASS FFMA2: only reachable via PTX) ----
__device__ __forceinline__ void ffma2(u64 &d, u64 a, u64 b){
    asm("fma.rn.f32x2 %0, %1, %2, %0;" : "+l"(d) : "l"(a), "l"(b));
}
__device__ __forceinline__ u64 pack2(float lo, float hi){
    u64 r; asm("mov.b64 %0, {%1, %2};" : "=l"(r) : "f"(lo), "f"(hi)); return r;
}
__device__ __forceinline__ float2 unpack2(u64 v){
    float2 r; asm("mov.b64 {%0, %1}, %2;" : "=f"(r.x), "=f"(r.y) : "l"(v)); return r;
}

// ---- fast activations: MUFU-based, rel err ~1e-6 ----
__device__ __forceinline__ float fex2(float x){ float r; asm("ex2.approx.f32 %0, %1;" : "=f"(r) : "f"(x)); return r; }
__device__ __forceinline__ float frcp(float x){ float r; asm("rcp.approx.f32 %0, %1;" : "=f"(r) : "f"(x)); return r; }
#define LOG2E 1.4426950408889634f
__device__ __forceinline__ float sigf(float x){
    return frcp(1.0f + fex2(-LOG2E*x));
}
__device__ __forceinline__ float tanhfast(float x){
    float t = fminf(2.0f*LOG2E*x, 126.0f);
    float e = fex2(t);
    return (e - 1.0f) * frcp(e + 1.0f);
}
__device__ __forceinline__ uint32_t f2tf32(float x){
    uint32_t r; asm("cvt.rna.tf32.f32 %0, %1;" : "=r"(r) : "f"(x)); return r;
}

// ---------------- device scratch ----------------
__device__ __align__(16) float g_l1_whhT[2][128*512];
__device__ __align__(16) float g_l1_wih [2][512];
__device__ __align__(16) float g_l1_b   [2][512];
__device__ __align__(16) float g_l2_wihT[2][256*512];
__device__ __align__(16) float g_l2_whhT[2][128*512];
__device__ __align__(16) float g_l2_b   [2][512];
__device__ __align__(16) float g_fc1_wT[256*256];
__device__ __align__(16) float g_fc2_wT[256*64];
__device__ __align__(16) float g_g1_whhT[128*512];
__device__ __align__(16) float g_g1_wih[512];
__device__ __align__(16) float g_g1_bih[512];
__device__ __align__(16) float g_g1_bhh[512];
__device__ __align__(16) float g_g2_wihT[128*160];
__device__ __align__(16) float g_g2_whhT[50*160];
__device__ __align__(16) float g_h1out[(size_t)T_SZ*B_SZ*256];      // [t][b][256]
__device__ __align__(16) float g_preact[2][(size_t)T_SZ*B_SZ*512];  // [dir][t*B+b][512]
__device__ __align__(16) float g_hn[4][B_SZ*128];
__device__ __align__(16) float g_hidden[B_SZ*128];

// ---------------- weight permutation (gate-quad layout: col = h*4+q) ----------------
__global__ void k_prep(
    const float* __restrict__ l1_wih_f, const float* __restrict__ l1_whh_f, const float* __restrict__ l1_b_f,
    const float* __restrict__ l1_wih_b, const float* __restrict__ l1_whh_b, const float* __restrict__ l1_b_b,
    const float* __restrict__ l2_wih_f, const float* __restrict__ l2_whh_f, const float* __restrict__ l2_b_f,
    const float* __restrict__ l2_wih_b, const float* __restrict__ l2_whh_b, const float* __restrict__ l2_b_b,
    const float* __restrict__ fc1_w, const float* __restrict__ fc2_w,
    const float* __restrict__ g1_wih, const float* __restrict__ g1_whh,
    const float* __restrict__ g1_bih, const float* __restrict__ g1_bhh,
    const float* __restrict__ g2_wih, const float* __restrict__ g2_whh)
{
    const int idx = blockIdx.x*blockDim.x + threadIdx.x;
    const int stride = gridDim.x*blockDim.x;

    for (int i=idx; i<2*128*512; i+=stride){
        int dir=i>>16, r=i&65535, k=r>>9, col=r&511, h=col>>2, q=col&3;
        const float* s = dir ? l1_whh_b : l1_whh_f;
        g_l1_whhT[dir][r] = s[(q*128+h)*128 + k];
    }
    for (int i=idx; i<2*128*512; i+=stride){
        int dir=i>>16, r=i&65535, k=r>>9, col=r&511, h=col>>2, q=col&3;
        const float* s = dir ? l2_whh_b : l2_whh_f;
        g_l2_whhT[dir][r] = s[(q*128+h)*128 + k];
    }
    for (int i=idx; i<2*256*512; i+=stride){
        int dir=i>>17, r=i&131071, k=r>>9, col=r&511, h=col>>2, q=col&3;
        const float* s = dir ? l2_wih_b : l2_wih_f;
        g_l2_wihT[dir][r] = s[(q*128+h)*256 + k];
    }
    for (int i=idx; i<2*512; i+=stride){
        int dir=i>>9, col=i&511, h=col>>2, q=col&3, g=q*128+h;
        g_l1_wih[dir][col] = (dir ? l1_wih_b : l1_wih_f)[g];
        g_l1_b  [dir][col] = (dir ? l1_b_b   : l1_b_f  )[g];
        g_l2_b  [dir][col] = (dir ? l2_b_b   : l2_b_f  )[g];
    }
    for (int i=idx; i<256*256; i+=stride){
        int c=i>>8, j=i&255;
        g_fc1_wT[i] = fc1_w[j*256+c];
    }
    for (int i=idx; i<256*64; i+=stride){
        int c=i>>6, j=i&63;
        g_fc2_wT[i] = fc2_w[j*256+c];
    }
    for (int i=idx; i<128*512; i+=stride){
        int k=i>>9, col=i&511, h=col>>2, q=col&3;
        g_g1_whhT[i] = (q<3) ? g1_whh[(q*128+h)*128 + k] : 0.0f;
    }
    for (int i=idx; i<512; i+=stride){
        int h=i>>2, q=i&3;
        g_g1_wih[i] = (q<3) ? g1_wih[q*128+h] : 0.0f;
        g_g1_bih[i] = (q<3) ? g1_bih[q*128+h] : 0.0f;
        g_g1_bhh[i] = (q<3) ? g1_bhh[q*128+h] : 0.0f;
    }
    for (int i=idx; i<128*160; i+=stride){
        int k=i/160, g=i%160;
        g_g2_wihT[i] = (g<150) ? g2_wih[g*128+k] : 0.0f;
    }
    for (int i=idx; i<50*160; i+=stride){
        int k=i/160, g=i%160;
        g_g2_whhT[i] = (g<150) ? g2_whh[g*50+k] : 0.0f;
    }
}

// ---------------- BiLSTM layer 1 (input dim 1): transposed h state (R10 best) ----------------
__global__ void __launch_bounds__(128) k_lstm1(const float* __restrict__ edge)
{
    const int dir = blockIdx.y;
    const int b0  = blockIdx.x * NB;
    const int hh  = threadIdx.x;

    __shared__ float sh_x[NB][T_SZ];
    __shared__ u64   sh_hT[128][18];

    for (int i = hh; i < NB*T_SZ; i += 128){
        int b = i / T_SZ, t = i % T_SZ;
        sh_x[b][t] = edge[(b0+b)*T_SZ + t];
    }
    #pragma unroll
    for (int j=0;j<NB;j++) sh_hT[hh][j] = 0ull;
    float c[NB];
    #pragma unroll
    for (int b=0;b<NB;b++) c[b] = 0.0f;
    float hb[NB];

    const ulonglong2* __restrict__ W = (const ulonglong2*)g_l1_whhT[dir];
    const u64* wib = (const u64*)g_l1_wih[dir];
    const u64* bbp = (const u64*)g_l1_b[dir];
    const u64 wi01 = wib[2*hh], wi23 = wib[2*hh+1];
    const u64 b01  = bbp[2*hh], b23  = bbp[2*hh+1];
    __syncthreads();

    for (int s=0; s<T_SZ; s++){
        const int t = dir ? (T_SZ-1-s) : s;
        u64 a01[NB], a23[NB];
        #pragma unroll
        for (int b=0;b<NB;b++){
            float xv = sh_x[b][t];
            u64 x2 = pack2(xv, xv);
            a01[b] = b01; ffma2(a01[b], wi01, x2);
            a23[b] = b23; ffma2(a23[b], wi23, x2);
        }
        #pragma unroll 4
        for (int k=0;k<128;k++){
            ulonglong2 w = W[k*128 + hh];
            const ulonglong2* hrow = (const ulonglong2*)sh_hT[k];
            #pragma unroll
            for (int j=0;j<8;j++){
                ulonglong2 hp = hrow[j];
                ffma2(a01[2*j],   w.x, hp.x);
                ffma2(a23[2*j],   w.y, hp.x);
                ffma2(a01[2*j+1], w.x, hp.y);
                ffma2(a23[2*j+1], w.y, hp.y);
            }
        }
        __syncthreads();
        float* outp = g_h1out + (size_t)t*(B_SZ*256) + (size_t)b0*256 + dir*128 + hh;
        #pragma unroll
        for (int b=0;b<NB;b++){
            float2 g01 = unpack2(a01[b]);
            float2 g23 = unpack2(a23[b]);
            float ig = sigf(g01.x);
            float fg = sigf(g01.y);
            float gg = tanhfast(g23.x);
            float og = sigf(g23.y);
            c[b] = fmaf(fg, c[b], ig*gg);
            hb[b] = og * tanhfast(c[b]);
            outp[b*256] = hb[b];
        }
        ulonglong2* myrow = (ulonglong2*)sh_hT[hh];
        #pragma unroll
        for (int j=0;j<8;j++)
            myrow[j] = make_ulonglong2(pack2(hb[2*j],hb[2*j]), pack2(hb[2*j+1],hb[2*j+1]));
        __syncthreads();
    }
    #pragma unroll
    for (int b=0;b<NB;b++) g_hn[dir][(b0+b)*128 + hh] = hb[b];
}

// ---------------- L2 input projection: tf32 tensor-core GEMM ----------------
// preact[dir] = h1out @ l2_wihT[dir] + bias.  M=409600, N=512, K=256.
// CTA tile 128x128, warp tile 64x32, mma.sync m16n8k8 tf32, fp32 accumulate.
__global__ void __launch_bounds__(256) k_proj()
{
    const int dir = blockIdx.z;
    const int c0  = blockIdx.y * 128;
    const size_t r0 = (size_t)blockIdx.x * 128;
    const int tid  = threadIdx.x;
    const int wid  = tid >> 5;
    const int lane = tid & 31;
    const int wm = wid >> 2;       // 0..1 : rows 64*wm
    const int wn = wid & 3;        // 0..3 : cols 32*wn
    const int g  = lane >> 2;      // groupID
    const int tg = lane & 3;       // threadID_in_group

    __shared__ float sA[128][36];  // pad 36: a-frag read bank = 4g+tg (bijective)
    __shared__ float sB[32][136];  // pad 136: b-frag read bank = 8tg+g (bijective)

    float acc[4][4][4];
    #pragma unroll
    for (int i=0;i<4;i++)
        #pragma unroll
        for (int j=0;j<4;j++)
            #pragma unroll
            for (int q=0;q<4;q++) acc[i][j][q] = 0.0f;

    const int arow = tid >> 1;
    const int acol = (tid & 1) * 16;
    const int brow = tid >> 3;
    const int bcol = (tid & 7) * 16;
    const float* __restrict__ Asrc = g_h1out + (r0 + arow)*256 + acol;
    const float* __restrict__ Bsrc = g_l2_wihT[dir] + (size_t)brow*512 + c0 + bcol;

    for (int ks=0; ks<256; ks+=32){
        __syncthreads();
        #pragma unroll
        for (int v=0; v<4; v++){
            float4 a = *(const float4*)(Asrc + ks + v*4);
            uint4 ua = make_uint4(f2tf32(a.x), f2tf32(a.y), f2tf32(a.z), f2tf32(a.w));
            *(uint4*)&sA[arow][acol + v*4] = ua;
        }
        #pragma unroll
        for (int v=0; v<4; v++){
            float4 b = *(const float4*)(Bsrc + (size_t)ks*512 + v*4);
            uint4 ub = make_uint4(f2tf32(b.x), f2tf32(b.y), f2tf32(b.z), f2tf32(b.w));
            *(uint4*)&sB[brow][bcol + v*4] = ub;
        }
        __syncthreads();

        #pragma unroll
        for (int kt=0; kt<4; kt++){
            uint32_t bf[4][2];
            #pragma unroll
            for (int j=0;j<4;j++){
                int col = wn*32 + j*8 + g;
                bf[j][0] = *(const uint32_t*)&sB[kt*8 + tg    ][col];
                bf[j][1] = *(const uint32_t*)&sB[kt*8 + tg + 4][col];
            }
            #pragma unroll
            for (int i=0;i<4;i++){
                int r = wm*64 + i*16;
                uint32_t a0 = *(const uint32_t*)&sA[r + g    ][kt*8 + tg    ];
                uint32_t a1 = *(const uint32_t*)&sA[r + g + 8][kt*8 + tg    ];
                uint32_t a2 = *(const uint32_t*)&sA[r + g    ][kt*8 + tg + 4];
                uint32_t a3 = *(const uint32_t*)&sA[r + g + 8][kt*8 + tg + 4];
                #pragma unroll
                for (int j=0;j<4;j++){
                    asm("mma.sync.aligned.m16n8k8.row.col.f32.tf32.tf32.f32 "
                        "{%0,%1,%2,%3}, {%4,%5,%6,%7}, {%8,%9}, {%0,%1,%2,%3};"
                        : "+f"(acc[i][j][0]), "+f"(acc[i][j][1]),
                          "+f"(acc[i][j][2]), "+f"(acc[i][j][3])
                        : "r"(a0), "r"(a1), "r"(a2), "r"(a3),
                          "r"(bf[j][0]), "r"(bf[j][1]));
                }
            }
        }
    }

    float* __restrict__ C = g_preact[dir];
    #pragma unroll
    for (int j=0;j<4;j++){
        int col = c0 + wn*32 + j*8 + 2*tg;
        float2 bias = *(const float2*)&g_l2_b[dir][col];
        #pragma unroll
        for (int i=0;i<4;i++){
            size_t rA = r0 + wm*64 + i*16 + g;
            float2 v0 = make_float2(acc[i][j][0]+bias.x, acc[i][j][1]+bias.y);
            float2 v1 = make_float2(acc[i][j][2]+bias.x, acc[i][j][3]+bias.y);
            *(float2*)&C[rA*512 + col]     = v0;
            *(float2*)&C[(rA+8)*512 + col] = v1;
        }
    }
}

// ---------------- BiLSTM layer 2: recurrent only, reads preact ----------------
__global__ void __launch_bounds__(128) k_lstm2()
{
    const int dir = blockIdx.y;
    const int b0  = blockIdx.x * NB;
    const int hh  = threadIdx.x;

    __shared__ u64 sh_hT[128][18];   // transposed duplicated {h,h}

    #pragma unroll
    for (int j=0;j<NB;j++) sh_hT[hh][j] = 0ull;
    float c[NB];
    #pragma unroll
    for (int b=0;b<NB;b++) c[b] = 0.0f;
    float hb[NB];

    const ulonglong2* __restrict__ Wh = (const ulonglong2*)g_l2_whhT[dir];
    const float* __restrict__ pre = g_preact[dir];
    __syncthreads();

    for (int s=0; s<T_SZ; s++){
        const int t = dir ? (T_SZ-1-s) : s;

        // preact loads (bias + Wx*x included), issued before the matvec
        float4 p[NB];
        #pragma unroll
        for (int b=0;b<NB;b++)
            p[b] = ((const float4*)(pre + ((size_t)t*B_SZ + b0 + b)*512))[hh];

        u64 a01[NB], a23[NB];
        #pragma unroll
        for (int b=0;b<NB;b++){ a01[b] = 0ull; a23[b] = 0ull; }

        #pragma unroll 4
        for (int k=0;k<128;k++){
            ulonglong2 w = Wh[k*128 + hh];
            const ulonglong2* hrow = (const ulonglong2*)sh_hT[k];
            #pragma unroll
            for (int j=0;j<8;j++){
                ulonglong2 hp = hrow[j];
                ffma2(a01[2*j],   w.x, hp.x);
                ffma2(a23[2*j],   w.y, hp.x);
                ffma2(a01[2*j+1], w.x, hp.y);
                ffma2(a23[2*j+1], w.y, hp.y);
            }
        }
        __syncthreads();   // all sh_hT reads done
        #pragma unroll
        for (int b=0;b<NB;b++){
            float2 g01 = unpack2(a01[b]);
            float2 g23 = unpack2(a23[b]);
            float ig = sigf(g01.x + p[b].x);
            float fg = sigf(g01.y + p[b].y);
            float gg = tanhfast(g23.x + p[b].z);
            float og = sigf(g23.y + p[b].w);
            c[b] = fmaf(fg, c[b], ig*gg);
            hb[b] = og * tanhfast(c[b]);
        }
        ulonglong2* myrow = (ulonglong2*)sh_hT[hh];
        #pragma unroll
        for (int j=0;j<8;j++)
            myrow[j] = make_ulonglong2(pack2(hb[2*j],hb[2*j]), pack2(hb[2*j+1],hb[2*j+1]));
        __syncthreads();
    }
    #pragma unroll
    for (int b=0;b<NB;b++) g_hn[2+dir][(b0+b)*128 + hh] = hb[b];
}

// ---------------- FC head ----------------
__global__ void __launch_bounds__(256) k_fc(const int* __restrict__ node_data,
                                            const float* __restrict__ emb,
                                            const float* __restrict__ fc1_b,
                                            const float* __restrict__ fc2_b)
{
    const int r = blockIdx.x;
    const int c = threadIdx.x;
    __shared__ float sh_in[256];
    __shared__ float sh_mid[256];

    int d = r >> 10;
    int b = ((r & 1023) << 1) + (c >> 7);
    int k = c & 127;
    sh_in[c] = g_hn[d][b*128 + k] + g_hn[2+d][b*128 + k];
    __syncthreads();

    float acc = fc1_b[c];
    #pragma unroll 4
    for (int i=0;i<256;i++) acc = fmaf(sh_in[i], g_fc1_wT[i*256 + c], acc);
    sh_mid[c] = sigf(acc);
    __syncthreads();

    if (c < 64){
        float a2 = fc2_b[c];
        #pragma unroll 4
        for (int i=0;i<256;i++) a2 = fmaf(sh_mid[i], g_fc2_wT[i*64 + c], a2);
        g_hidden[r*128 + c] = sigf(a2);
    } else if (c < 128){
        int e = c - 64;
        int n0 = node_data[r*2], n1 = node_data[r*2+1];
        g_hidden[r*128 + 64 + e] = 0.5f*(emb[n0*64 + e] + emb[n1*64 + e]);
    }
}

// ---------------- decoder: GRU(128) -> GRU(50) -> sigmoid, 200 steps ----------------
__global__ void __launch_bounds__(160) k_dec(const float* __restrict__ edge,
                                             const float* __restrict__ g2_bih,
                                             const float* __restrict__ g2_bhh,
                                             const float* __restrict__ dec_w,
                                             const float* __restrict__ dec_b,
                                             float* __restrict__ out)
{
    const int b0  = blockIdx.x * NB;
    const int tid = threadIdx.x;     // 0..159

    __shared__ u64   h1dT[128][18];
    __shared__ u64   h1p[128][9];
    __shared__ u64   h2p[52][9];
    __shared__ float h2s[NB][52];
    __shared__ float s_rz[NB][100];
    __shared__ float s_in[NB][52];
    __shared__ float s_hn[NB][52];
    __shared__ float res[NB];
    __shared__ float dw[52];

    if (tid < 128){
        float v[NB];
        #pragma unroll
        for (int b=0;b<NB;b++) v[b] = g_hidden[(b0+b)*128 + tid];
        ulonglong2* myrow = (ulonglong2*)h1dT[tid];
        #pragma unroll
        for (int j=0;j<8;j++)
            myrow[j] = make_ulonglong2(pack2(v[2*j],v[2*j]), pack2(v[2*j+1],v[2*j+1]));
        #pragma unroll
        for (int bp=0;bp<8;bp++) h1p[tid][bp] = pack2(v[2*bp], v[2*bp+1]);
    }
    if (tid < 52){
        #pragma unroll
        for (int b=0;b<NB;b++) h2s[b][tid] = 0.0f;
        #pragma unroll
        for (int bp=0;bp<8;bp++) h2p[tid][bp] = 0ull;
        dw[tid] = (tid < 50) ? dec_w[tid] : 0.0f;
    }
    if (tid < NB) res[tid] = edge[(b0+tid)*T_SZ + (T_SZ-1)];

    float4 wi = {0,0,0,0}, bi = {0,0,0,0}, bh = {0,0,0,0};
    if (tid < 128){
        wi = ((const float4*)g_g1_wih)[tid];
        bi = ((const float4*)g_g1_bih)[tid];
        bh = ((const float4*)g_g1_bhh)[tid];
    }
    float g2bi = 0.0f, g2bh = 0.0f;
    if (tid < 150){ g2bi = g2_bih[tid]; g2bh = g2_bhh[tid]; }
    const float decb = dec_b[0];
    __syncthreads();

    for (int t=0; t<T_SZ; t++){
        u64 a01[NB], a23[NB];
        if (tid < 128){
            const u64 bh01 = pack2(bh.x, bh.y);
            const u64 bh23 = pack2(bh.z, bh.w);
            #pragma unroll
            for (int b=0;b<NB;b++){ a01[b] = bh01; a23[b] = bh23; }
            const ulonglong2* __restrict__ W = (const ulonglong2*)g_g1_whhT;
            #pragma unroll 4
            for (int k=0;k<128;k++){
                ulonglong2 w = W[k*128 + tid];
                const ulonglong2* hrow = (const ulonglong2*)h1dT[k];
                #pragma unroll
                for (int j=0;j<8;j++){
                    ulonglong2 hp = hrow[j];
                    ffma2(a01[2*j],   w.x, hp.x);
                    ffma2(a23[2*j],   w.y, hp.x);
                    ffma2(a01[2*j+1], w.x, hp.y);
                    ffma2(a23[2*j+1], w.y, hp.y);
                }
            }
        }
        __syncthreads();

        if (tid < 128){
            float hn_[NB];
            #pragma unroll
            for (int b=0;b<NB;b++){
                float2 g01 = unpack2(a01[b]);
                float2 g23 = unpack2(a23[b]);
                float rv  = res[b];
                float ir  = fmaf(rv, wi.x, bi.x);
                float iz  = fmaf(rv, wi.y, bi.y);
                float inn = fmaf(rv, wi.z, bi.z);
                float rg = sigf(ir + g01.x);
                float zg = sigf(iz + g01.y);
                float ng = tanhfast(fmaf(rg, g23.x, inn));
                float h1 = unpack2(h1dT[tid][b]).x;
                hn_[b] = fmaf(zg, h1 - ng, ng);
            }
            ulonglong2* myrow = (ulonglong2*)h1dT[tid];
            #pragma unroll
            for (int j=0;j<8;j++)
                myrow[j] = make_ulonglong2(pack2(hn_[2*j],hn_[2*j]), pack2(hn_[2*j+1],hn_[2*j+1]));
            #pragma unroll
            for (int bp=0;bp<8;bp++) h1p[tid][bp] = pack2(hn_[2*bp], hn_[2*bp+1]);
        }
        __syncthreads();

        if (tid < 150){
            u64 gi2[8], gh2[8];
            const u64 bi2 = pack2(g2bi, g2bi);
            const u64 bh2 = pack2(g2bh, g2bh);
            #pragma unroll
            for (int bp=0;bp<8;bp++){ gi2[bp] = bi2; gh2[bp] = bh2; }
            #pragma unroll 4
            for (int k=0;k<128;k++){
                float w = g_g2_wihT[k*160 + tid];
                u64 w2 = pack2(w, w);
                #pragma unroll
                for (int bp=0;bp<8;bp++) ffma2(gi2[bp], h1p[k][bp], w2);
            }
            #pragma unroll 2
            for (int k=0;k<50;k++){
                float w = g_g2_whhT[k*160 + tid];
                u64 w2 = pack2(w, w);
                #pragma unroll
                for (int bp=0;bp<8;bp++) ffma2(gh2[bp], h2p[k][bp], w2);
            }
            if (tid < 100){
                #pragma unroll
                for (int bp=0;bp<8;bp++){
                    float2 a = unpack2(gi2[bp]);
                    float2 b = unpack2(gh2[bp]);
                    s_rz[2*bp][tid]   = a.x + b.x;
                    s_rz[2*bp+1][tid] = a.y + b.y;
                }
            } else {
                int n = tid - 100;
                #pragma unroll
                for (int bp=0;bp<8;bp++){
                    float2 a = unpack2(gi2[bp]);
                    float2 b = unpack2(gh2[bp]);
                    s_in[2*bp][n]   = a.x;  s_hn[2*bp][n]   = b.x;
                    s_in[2*bp+1][n] = a.y;  s_hn[2*bp+1][n] = b.y;
                }
            }
        }
        __syncthreads();

        if (tid < 50){
            float h2n[NB];
            #pragma unroll
            for (int b=0;b<NB;b++){
                float rg = sigf(s_rz[b][tid]);
                float zg = sigf(s_rz[b][50+tid]);
                float ng = tanhfast(fmaf(rg, s_hn[b][tid], s_in[b][tid]));
                float h2 = h2s[b][tid];
                h2n[b] = fmaf(zg, h2 - ng, ng);
                h2s[b][tid] = h2n[b];
            }
            #pragma unroll
            for (int bp=0;bp<8;bp++) h2p[tid][bp] = pack2(h2n[2*bp], h2n[2*bp+1]);
        }
        __syncthreads();

        if (tid < NB){
            float s = decb;
            #pragma unroll 2
            for (int k=0;k<50;k++) s = fmaf(h2s[tid][k], dw[k], s);
            float r = sigf(s);
            res[tid] = r;
            out[(b0+tid)*T_SZ + t] = r;
        }
        __syncthreads();
    }
}

extern "C" void kernel_launch(void* const* d_in, const int* in_sizes, int n_in,
                              void* d_out, int out_size)
{
    const int*   node_data = (const int*)  d_in[0];
    const float* edge_data = (const float*)d_in[1];
    const float* emb       = (const float*)d_in[2];
    const float* l1_wih_f  = (const float*)d_in[3];
    const float* l1_whh_f  = (const float*)d_in[4];
    const float* l1_b_f    = (const float*)d_in[5];
    const float* l1_wih_b  = (const float*)d_in[6];
    const float* l1_whh_b  = (const float*)d_in[7];
    const float* l1_b_b    = (const float*)d_in[8];
    const float* l2_wih_f  = (const float*)d_in[9];
    const float* l2_whh_f  = (const float*)d_in[10];
    const float* l2_b_f    = (const float*)d_in[11];
    const float* l2_wih_b  = (const float*)d_in[12];
    const float* l2_whh_b  = (const float*)d_in[13];
    const float* l2_b_b    = (const float*)d_in[14];
    const float* fc1_w     = (const float*)d_in[15];
    const float* fc1_b     = (const float*)d_in[16];
    const float* fc2_w     = (const float*)d_in[17];
    const float* fc2_b     = (const float*)d_in[18];
    const float* g1_wih    = (const float*)d_in[19];
    const float* g1_whh    = (const float*)d_in[20];
    const float* g1_bih    = (const float*)d_in[21];
    const float* g1_bhh    = (const float*)d_in[22];
    const float* g2_wih    = (const float*)d_in[23];
    const float* g2_whh    = (const float*)d_in[24];
    const float* g2_bih    = (const float*)d_in[25];
    const float* g2_bhh    = (const float*)d_in[26];
    const float* dec_w     = (const float*)d_in[27];
    const float* dec_b     = (const float*)d_in[28];
    float* out = (float*)d_out;

    k_prep<<<256, 256>>>(l1_wih_f, l1_whh_f, l1_b_f, l1_wih_b, l1_whh_b, l1_b_b,
                         l2_wih_f, l2_whh_f, l2_b_f, l2_wih_b, l2_whh_b, l2_b_b,
                         fc1_w, fc2_w, g1_wih, g1_whh, g1_bih, g1_bhh,
                         g2_wih, g2_whh);
    k_lstm1<<<dim3(B_SZ/NB, 2), 128>>>(edge_data);
    k_proj<<<dim3((T_SZ*B_SZ)/128, 4, 2), 256>>>();
    k_lstm2<<<dim3(B_SZ/NB, 2), 128>>>();
    k_fc<<<B_SZ, 256>>>(node_data, emb, fc1_b, fc2_b);
    k_dec<<<B_SZ/NB, 160>>>(edge_data, g2_bih, g2_bhh, dec_w, dec_b, out);
}

// round 14
// speedup vs baseline: 1.5612x; 1.2121x over previous
#include <cuda_runtime.h>
#include <math.h>
#include <stdint.h>

#define B_SZ 2048
#define T_SZ 200
#define NB   16

typedef unsigned long long u64;

// ---- packed fp32x2 helpers ----
__device__ __forceinline__ void ffma2(u64 &d, u64 a, u64 b){
    asm("fma.rn.f32x2 %0, %1, %2, %0;" : "+l"(d) : "l"(a), "l"(b));
}
__device__ __forceinline__ u64 pack2(float lo, float hi){
    u64 r; asm("mov.b64 %0, {%1, %2};" : "=l"(r) : "f"(lo), "f"(hi)); return r;
}
__device__ __forceinline__ float2 unpack2(u64 v){
    float2 r; asm("mov.b64 {%0, %1}, %2;" : "=f"(r.x), "=f"(r.y) : "l"(v)); return r;
}

// ---- fast activations ----
__device__ __forceinline__ float fex2(float x){ float r; asm("ex2.approx.f32 %0, %1;" : "=f"(r) : "f"(x)); return r; }
__device__ __forceinline__ float frcp(float x){ float r; asm("rcp.approx.f32 %0, %1;" : "=f"(r) : "f"(x)); return r; }
#define LOG2E 1.4426950408889634f
__device__ __forceinline__ float sigf(float x){
    return frcp(1.0f + fex2(-LOG2E*x));
}
__device__ __forceinline__ float tanhfast(float x){
    float t = fminf(2.0f*LOG2E*x, 126.0f);
    float e = fex2(t);
    return (e - 1.0f) * frcp(e + 1.0f);
}
__device__ __forceinline__ uint32_t f2tf32(float x){
    uint32_t r; asm("cvt.rna.tf32.f32 %0, %1;" : "=r"(r) : "f"(x)); return r;
}

// ---------------- device scratch ----------------
__device__ __align__(16) float g_l1_whhF[2][65536];   // frag-linear tf32 recurrent weights
__device__ __align__(16) float g_l2_whhF[2][65536];
__device__ __align__(16) float g_l1_wih [2][512];
__device__ __align__(16) float g_l1_b   [2][512];
__device__ __align__(16) float g_l2_wihT[2][256*512];
__device__ __align__(16) float g_l2_b   [2][512];
__device__ __align__(16) float g_fc1_wT[256*256];
__device__ __align__(16) float g_fc2_wT[256*64];
__device__ __align__(16) float g_g1_whhT[128*512];
__device__ __align__(16) float g_g1_wih[512];
__device__ __align__(16) float g_g1_bih[512];
__device__ __align__(16) float g_g1_bhh[512];
__device__ __align__(16) float g_g2_wihT[128*160];
__device__ __align__(16) float g_g2_whhT[50*160];
__device__ __align__(16) float g_h1out[(size_t)T_SZ*B_SZ*256];      // [t][b][256]
__device__ __align__(16) float g_preact[2][(size_t)T_SZ*B_SZ*512];  // [dir][t*B+b][512]
__device__ __align__(16) float g_hn[4][B_SZ*128];
__device__ __align__(16) float g_hidden[B_SZ*128];

// ---------------- weight permutation ----------------
// Gate-quad column layout: col = h*4+q maps to source gate row q*128+h.
// Frag-linear recurrent W: word idx = ((w*16+kt)*8 + j)*64 + lane*2 + r,
// element = W[col = w*64+j*8+g][k = kt*8+tg+4r], stored as tf32 bits.
__global__ void k_prep(
    const float* __restrict__ l1_wih_f, const float* __restrict__ l1_whh_f, const float* __restrict__ l1_b_f,
    const float* __restrict__ l1_wih_b, const float* __restrict__ l1_whh_b, const float* __restrict__ l1_b_b,
    const float* __restrict__ l2_wih_f, const float* __restrict__ l2_whh_f, const float* __restrict__ l2_b_f,
    const float* __restrict__ l2_wih_b, const float* __restrict__ l2_whh_b, const float* __restrict__ l2_b_b,
    const float* __restrict__ fc1_w, const float* __restrict__ fc2_w,
    const float* __restrict__ g1_wih, const float* __restrict__ g1_whh,
    const float* __restrict__ g1_bih, const float* __restrict__ g1_bhh,
    const float* __restrict__ g2_wih, const float* __restrict__ g2_whh)
{
    const int idx = blockIdx.x*blockDim.x + threadIdx.x;
    const int stride = gridDim.x*blockDim.x;

    for (int i=idx; i<2*65536; i+=stride){            // frag-linear recurrent weights
        int dir = i>>16, x = i&65535;
        int r = x&1, lane = (x>>1)&31, j = (x>>6)&7, kt = (x>>9)&15, w = (x>>13)&7;
        int g = lane>>2, tg = lane&3;
        int k = kt*8 + tg + 4*r;
        int col = w*64 + j*8 + g;
        int srow = (col&3)*128 + (col>>2);
        const float* s1 = dir ? l1_whh_b : l1_whh_f;
        const float* s2 = dir ? l2_whh_b : l2_whh_f;
        g_l1_whhF[dir][x] = __uint_as_float(f2tf32(s1[srow*128 + k]));
        g_l2_whhF[dir][x] = __uint_as_float(f2tf32(s2[srow*128 + k]));
    }
    for (int i=idx; i<2*256*512; i+=stride){          // L2 wih^T (for k_proj)
        int dir=i>>17, r=i&131071, k=r>>9, col=r&511, h=col>>2, q=col&3;
        const float* s = dir ? l2_wih_b : l2_wih_f;
        g_l2_wihT[dir][r] = s[(q*128+h)*256 + k];
    }
    for (int i=idx; i<2*512; i+=stride){
        int dir=i>>9, col=i&511, h=col>>2, q=col&3, g=q*128+h;
        g_l1_wih[dir][col] = (dir ? l1_wih_b : l1_wih_f)[g];
        g_l1_b  [dir][col] = (dir ? l1_b_b   : l1_b_f  )[g];
        g_l2_b  [dir][col] = (dir ? l2_b_b   : l2_b_f  )[g];
    }
    for (int i=idx; i<256*256; i+=stride){
        int c=i>>8, j=i&255;
        g_fc1_wT[i] = fc1_w[j*256+c];
    }
    for (int i=idx; i<256*64; i+=stride){
        int c=i>>6, j=i&63;
        g_fc2_wT[i] = fc2_w[j*256+c];
    }
    for (int i=idx; i<128*512; i+=stride){
        int k=i>>9, col=i&511, h=col>>2, q=col&3;
        g_g1_whhT[i] = (q<3) ? g1_whh[(q*128+h)*128 + k] : 0.0f;
    }
    for (int i=idx; i<512; i+=stride){
        int h=i>>2, q=i&3;
        g_g1_wih[i] = (q<3) ? g1_wih[q*128+h] : 0.0f;
        g_g1_bih[i] = (q<3) ? g1_bih[q*128+h] : 0.0f;
        g_g1_bhh[i] = (q<3) ? g1_bhh[q*128+h] : 0.0f;
    }
    for (int i=idx; i<128*160; i+=stride){
        int k=i/160, g=i%160;
        g_g2_wihT[i] = (g<150) ? g2_wih[g*128+k] : 0.0f;
    }
    for (int i=idx; i<50*160; i+=stride){
        int k=i/160, g=i%160;
        g_g2_whhT[i] = (g<150) ? g2_whh[g*50+k] : 0.0f;
    }
}

// ---------------- BiLSTM layer 1: tensor-core scan, 32 batch rows/CTA ----------------
// smem: sA u32[32][132] tf32 h-state | sG float[32][520] gates | sx float[32][200]
__global__ void __launch_bounds__(256) k_lstm1(const float* __restrict__ edge)
{
    extern __shared__ char smem[];
    uint32_t* sA = (uint32_t*)smem;                 // 16896 B
    float*    sG = (float*)(smem + 16896);          // 66560 B
    float*    sx = (float*)(smem + 83456);          // 25600 B

    const int dir = blockIdx.y;
    const int b0  = blockIdx.x * 32;
    const int tid = threadIdx.x;
    const int wid = tid >> 5, lane = tid & 31;
    const int g   = lane >> 2, tg = lane & 3;
    const int hh  = tid & 127, half = tid >> 7;

    for (int i=tid; i<32*T_SZ; i+=256){
        int b = i / T_SZ, t = i % T_SZ;
        sx[b*T_SZ + t] = edge[(b0+b)*T_SZ + t];
    }
    for (int i=tid; i<32*132; i+=256) sA[i] = 0u;

    float c[16];
    #pragma unroll
    for (int q=0;q<16;q++) c[q] = 0.0f;

    const float4 wi = ((const float4*)g_l1_wih[dir])[hh];
    const float4 bb = ((const float4*)g_l1_b[dir])[hh];
    const u64* __restrict__ WF = (const u64*)g_l1_whhF[dir];
    __syncthreads();

    for (int s=0; s<T_SZ; s++){
        const int t = dir ? (T_SZ-1-s) : s;

        float acc[2][8][4];
        #pragma unroll
        for (int mi=0;mi<2;mi++)
            #pragma unroll
            for (int j=0;j<8;j++)
                #pragma unroll
                for (int q=0;q<4;q++) acc[mi][j][q] = 0.0f;

        #pragma unroll
        for (int kt=0;kt<16;kt++){
            uint32_t a[2][4];
            #pragma unroll
            for (int mi=0;mi<2;mi++){
                int rr = mi*16 + g;
                a[mi][0] = sA[rr*132     + kt*8 + tg];
                a[mi][1] = sA[(rr+8)*132 + kt*8 + tg];
                a[mi][2] = sA[rr*132     + kt*8 + tg + 4];
                a[mi][3] = sA[(rr+8)*132 + kt*8 + tg + 4];
            }
            #pragma unroll
            for (int j=0;j<8;j++){
                u64 wv = WF[((wid*16 + kt)*8 + j)*32 + lane];
                uint32_t bw0 = (uint32_t)wv, bw1 = (uint32_t)(wv>>32);
                #pragma unroll
                for (int mi=0;mi<2;mi++){
                    asm("mma.sync.aligned.m16n8k8.row.col.f32.tf32.tf32.f32 "
                        "{%0,%1,%2,%3}, {%4,%5,%6,%7}, {%8,%9}, {%0,%1,%2,%3};"
                        : "+f"(acc[mi][j][0]), "+f"(acc[mi][j][1]),
                          "+f"(acc[mi][j][2]), "+f"(acc[mi][j][3])
                        : "r"(a[mi][0]), "r"(a[mi][1]), "r"(a[mi][2]), "r"(a[mi][3]),
                          "r"(bw0), "r"(bw1));
                }
            }
        }
        // store gates to sG
        #pragma unroll
        for (int mi=0;mi<2;mi++){
            #pragma unroll
            for (int j=0;j<8;j++){
                int row = mi*16 + g, colb = wid*64 + j*8 + 2*tg;
                *(float2*)&sG[row*520 + colb]     = make_float2(acc[mi][j][0], acc[mi][j][1]);
                *(float2*)&sG[(row+8)*520 + colb] = make_float2(acc[mi][j][2], acc[mi][j][3]);
            }
        }
        __syncthreads();

        // epilogue: thread = (hidden hh, batch half)
        float* outp = g_h1out + (size_t)t*(B_SZ*256) + (size_t)(b0 + half*16)*256 + dir*128 + hh;
        #pragma unroll
        for (int q=0;q<16;q++){
            int b = half*16 + q;
            float4 gt = *(float4*)&sG[b*520 + 4*hh];
            float xv = sx[b*T_SZ + t];
            float gi = fmaf(wi.x, xv, gt.x + bb.x);
            float gf = fmaf(wi.y, xv, gt.y + bb.y);
            float gg = fmaf(wi.z, xv, gt.z + bb.z);
            float go = fmaf(wi.w, xv, gt.w + bb.w);
            float ig = sigf(gi), fg = sigf(gf), cg = tanhfast(gg), og = sigf(go);
            c[q] = fmaf(fg, c[q], ig*cg);
            float h = og * tanhfast(c[q]);
            sA[b*132 + hh] = f2tf32(h);
            outp[q*256] = h;
            if (s == T_SZ-1) g_hn[dir][(b0+b)*128 + hh] = h;
        }
        __syncthreads();
    }
}

// ---------------- L2 input projection: tf32 tensor-core GEMM (unchanged, proven) ----------------
__global__ void __launch_bounds__(256) k_proj()
{
    const int dir = blockIdx.z;
    const int c0  = blockIdx.y * 128;
    const size_t r0 = (size_t)blockIdx.x * 128;
    const int tid  = threadIdx.x;
    const int wid  = tid >> 5;
    const int lane = tid & 31;
    const int wm = wid >> 2;
    const int wn = wid & 3;
    const int g  = lane >> 2;
    const int tg = lane & 3;

    __shared__ float sA[128][36];
    __shared__ float sB[32][136];

    float acc[4][4][4];
    #pragma unroll
    for (int i=0;i<4;i++)
        #pragma unroll
        for (int j=0;j<4;j++)
            #pragma unroll
            for (int q=0;q<4;q++) acc[i][j][q] = 0.0f;

    const int arow = tid >> 1;
    const int acol = (tid & 1) * 16;
    const int brow = tid >> 3;
    const int bcol = (tid & 7) * 16;
    const float* __restrict__ Asrc = g_h1out + (r0 + arow)*256 + acol;
    const float* __restrict__ Bsrc = g_l2_wihT[dir] + (size_t)brow*512 + c0 + bcol;

    for (int ks=0; ks<256; ks+=32){
        __syncthreads();
        #pragma unroll
        for (int v=0; v<4; v++){
            float4 a = *(const float4*)(Asrc + ks + v*4);
            uint4 ua = make_uint4(f2tf32(a.x), f2tf32(a.y), f2tf32(a.z), f2tf32(a.w));
            *(uint4*)&sA[arow][acol + v*4] = ua;
        }
        #pragma unroll
        for (int v=0; v<4; v++){
            float4 b = *(const float4*)(Bsrc + (size_t)ks*512 + v*4);
            uint4 ub = make_uint4(f2tf32(b.x), f2tf32(b.y), f2tf32(b.z), f2tf32(b.w));
            *(uint4*)&sB[brow][bcol + v*4] = ub;
        }
        __syncthreads();

        #pragma unroll
        for (int kt=0; kt<4; kt++){
            uint32_t bf[4][2];
            #pragma unroll
            for (int j=0;j<4;j++){
                int col = wn*32 + j*8 + g;
                bf[j][0] = *(const uint32_t*)&sB[kt*8 + tg    ][col];
                bf[j][1] = *(const uint32_t*)&sB[kt*8 + tg + 4][col];
            }
            #pragma unroll
            for (int i=0;i<4;i++){
                int r = wm*64 + i*16;
                uint32_t a0 = *(const uint32_t*)&sA[r + g    ][kt*8 + tg    ];
                uint32_t a1 = *(const uint32_t*)&sA[r + g + 8][kt*8 + tg    ];
                uint32_t a2 = *(const uint32_t*)&sA[r + g    ][kt*8 + tg + 4];
                uint32_t a3 = *(const uint32_t*)&sA[r + g + 8][kt*8 + tg + 4];
                #pragma unroll
                for (int j=0;j<4;j++){
                    asm("mma.sync.aligned.m16n8k8.row.col.f32.tf32.tf32.f32 "
                        "{%0,%1,%2,%3}, {%4,%5,%6,%7}, {%8,%9}, {%0,%1,%2,%3};"
                        : "+f"(acc[i][j][0]), "+f"(acc[i][j][1]),
                          "+f"(acc[i][j][2]), "+f"(acc[i][j][3])
                        : "r"(a0), "r"(a1), "r"(a2), "r"(a3),
                          "r"(bf[j][0]), "r"(bf[j][1]));
                }
            }
        }
    }

    float* __restrict__ C = g_preact[dir];
    #pragma unroll
    for (int j=0;j<4;j++){
        int col = c0 + wn*32 + j*8 + 2*tg;
        float2 bias = *(const float2*)&g_l2_b[dir][col];
        #pragma unroll
        for (int i=0;i<4;i++){
            size_t rA = r0 + wm*64 + i*16 + g;
            float2 v0 = make_float2(acc[i][j][0]+bias.x, acc[i][j][1]+bias.y);
            float2 v1 = make_float2(acc[i][j][2]+bias.x, acc[i][j][3]+bias.y);
            *(float2*)&C[rA*512 + col]     = v0;
            *(float2*)&C[(rA+8)*512 + col] = v1;
        }
    }
}

// ---------------- BiLSTM layer 2: tensor-core recurrent scan (reads preact) ----------------
__global__ void __launch_bounds__(256) k_lstm2()
{
    extern __shared__ char smem[];
    uint32_t* sA = (uint32_t*)smem;                 // 16896 B
    float*    sG = (float*)(smem + 16896);          // 66560 B

    const int dir = blockIdx.y;
    const int b0  = blockIdx.x * 32;
    const int tid = threadIdx.x;
    const int wid = tid >> 5, lane = tid & 31;
    const int g   = lane >> 2, tg = lane & 3;
    const int hh  = tid & 127, half = tid >> 7;

    for (int i=tid; i<32*132; i+=256) sA[i] = 0u;
    float c[16];
    #pragma unroll
    for (int q=0;q<16;q++) c[q] = 0.0f;

    const u64* __restrict__ WF = (const u64*)g_l2_whhF[dir];
    const float* __restrict__ pre = g_preact[dir];
    __syncthreads();

    for (int s=0; s<T_SZ; s++){
        const int t = dir ? (T_SZ-1-s) : s;

        float acc[2][8][4];
        #pragma unroll
        for (int mi=0;mi<2;mi++)
            #pragma unroll
            for (int j=0;j<8;j++)
                #pragma unroll
                for (int q=0;q<4;q++) acc[mi][j][q] = 0.0f;

        #pragma unroll
        for (int kt=0;kt<16;kt++){
            uint32_t a[2][4];
            #pragma unroll
            for (int mi=0;mi<2;mi++){
                int rr = mi*16 + g;
                a[mi][0] = sA[rr*132     + kt*8 + tg];
                a[mi][1] = sA[(rr+8)*132 + kt*8 + tg];
                a[mi][2] = sA[rr*132     + kt*8 + tg + 4];
                a[mi][3] = sA[(rr+8)*132 + kt*8 + tg + 4];
            }
            #pragma unroll
            for (int j=0;j<8;j++){
                u64 wv = WF[((wid*16 + kt)*8 + j)*32 + lane];
                uint32_t bw0 = (uint32_t)wv, bw1 = (uint32_t)(wv>>32);
                #pragma unroll
                for (int mi=0;mi<2;mi++){
                    asm("mma.sync.aligned.m16n8k8.row.col.f32.tf32.tf32.f32 "
                        "{%0,%1,%2,%3}, {%4,%5,%6,%7}, {%8,%9}, {%0,%1,%2,%3};"
                        : "+f"(acc[mi][j][0]), "+f"(acc[mi][j][1]),
                          "+f"(acc[mi][j][2]), "+f"(acc[mi][j][3])
                        : "r"(a[mi][0]), "r"(a[mi][1]), "r"(a[mi][2]), "r"(a[mi][3]),
                          "r"(bw0), "r"(bw1));
                }
            }
        }
        #pragma unroll
        for (int mi=0;mi<2;mi++){
            #pragma unroll
            for (int j=0;j<8;j++){
                int row = mi*16 + g, colb = wid*64 + j*8 + 2*tg;
                *(float2*)&sG[row*520 + colb]     = make_float2(acc[mi][j][0], acc[mi][j][1]);
                *(float2*)&sG[(row+8)*520 + colb] = make_float2(acc[mi][j][2], acc[mi][j][3]);
            }
        }
        __syncthreads();

        #pragma unroll 4
        for (int q=0;q<16;q++){
            int b = half*16 + q;
            float4 gt = *(float4*)&sG[b*520 + 4*hh];
            float4 p  = *(const float4*)&pre[((size_t)t*B_SZ + b0 + b)*512 + 4*hh];
            float ig = sigf(gt.x + p.x);
            float fg = sigf(gt.y + p.y);
            float cg = tanhfast(gt.z + p.z);
            float og = sigf(gt.w + p.w);
            c[q] = fmaf(fg, c[q], ig*cg);
            float h = og * tanhfast(c[q]);
            sA[b*132 + hh] = f2tf32(h);
            if (s == T_SZ-1) g_hn[2+dir][(b0+b)*128 + hh] = h;
        }
        __syncthreads();
    }
}

// ---------------- FC head ----------------
__global__ void __launch_bounds__(256) k_fc(const int* __restrict__ node_data,
                                            const float* __restrict__ emb,
                                            const float* __restrict__ fc1_b,
                                            const float* __restrict__ fc2_b)
{
    const int r = blockIdx.x;
    const int c = threadIdx.x;
    __shared__ float sh_in[256];
    __shared__ float sh_mid[256];

    int d = r >> 10;
    int b = ((r & 1023) << 1) + (c >> 7);
    int k = c & 127;
    sh_in[c] = g_hn[d][b*128 + k] + g_hn[2+d][b*128 + k];
    __syncthreads();

    float acc = fc1_b[c];
    #pragma unroll 4
    for (int i=0;i<256;i++) acc = fmaf(sh_in[i], g_fc1_wT[i*256 + c], acc);
    sh_mid[c] = sigf(acc);
    __syncthreads();

    if (c < 64){
        float a2 = fc2_b[c];
        #pragma unroll 4
        for (int i=0;i<256;i++) a2 = fmaf(sh_mid[i], g_fc2_wT[i*64 + c], a2);
        g_hidden[r*128 + c] = sigf(a2);
    } else if (c < 128){
        int e = c - 64;
        int n0 = node_data[r*2], n1 = node_data[r*2+1];
        g_hidden[r*128 + 64 + e] = 0.5f*(emb[n0*64 + e] + emb[n1*64 + e]);
    }
}

// ---------------- decoder: GRU(128) -> GRU(50) -> sigmoid, 200 steps ----------------
__global__ void __launch_bounds__(160) k_dec(const float* __restrict__ edge,
                                             const float* __restrict__ g2_bih,
                                             const float* __restrict__ g2_bhh,
                                             const float* __restrict__ dec_w,
                                             const float* __restrict__ dec_b,
                                             float* __restrict__ out)
{
    const int b0  = blockIdx.x * NB;
    const int tid = threadIdx.x;

    __shared__ u64   h1dT[128][18];
    __shared__ u64   h1p[128][9];
    __shared__ u64   h2p[52][9];
    __shared__ float h2s[NB][52];
    __shared__ float s_rz[NB][100];
    __shared__ float s_in[NB][52];
    __shared__ float s_hn[NB][52];
    __shared__ float res[NB];
    __shared__ float dw[52];

    if (tid < 128){
        float v[NB];
        #pragma unroll
        for (int b=0;b<NB;b++) v[b] = g_hidden[(b0+b)*128 + tid];
        ulonglong2* myrow = (ulonglong2*)h1dT[tid];
        #pragma unroll
        for (int j=0;j<8;j++)
            myrow[j] = make_ulonglong2(pack2(v[2*j],v[2*j]), pack2(v[2*j+1],v[2*j+1]));
        #pragma unroll
        for (int bp=0;bp<8;bp++) h1p[tid][bp] = pack2(v[2*bp], v[2*bp+1]);
    }
    if (tid < 52){
        #pragma unroll
        for (int b=0;b<NB;b++) h2s[b][tid] = 0.0f;
        #pragma unroll
        for (int bp=0;bp<8;bp++) h2p[tid][bp] = 0ull;
        dw[tid] = (tid < 50) ? dec_w[tid] : 0.0f;
    }
    if (tid < NB) res[tid] = edge[(b0+tid)*T_SZ + (T_SZ-1)];

    float4 wi = {0,0,0,0}, bi = {0,0,0,0}, bh = {0,0,0,0};
    if (tid < 128){
        wi = ((const float4*)g_g1_wih)[tid];
        bi = ((const float4*)g_g1_bih)[tid];
        bh = ((const float4*)g_g1_bhh)[tid];
    }
    float g2bi = 0.0f, g2bh = 0.0f;
    if (tid < 150){ g2bi = g2_bih[tid]; g2bh = g2_bhh[tid]; }
    const float decb = dec_b[0];
    __syncthreads();

    for (int t=0; t<T_SZ; t++){
        u64 a01[NB], a23[NB];
        if (tid < 128){
            const u64 bh01 = pack2(bh.x, bh.y);
            const u64 bh23 = pack2(bh.z, bh.w);
            #pragma unroll
            for (int b=0;b<NB;b++){ a01[b] = bh01; a23[b] = bh23; }
            const ulonglong2* __restrict__ W = (const ulonglong2*)g_g1_whhT;
            #pragma unroll 4
            for (int k=0;k<128;k++){
                ulonglong2 w = W[k*128 + tid];
                const ulonglong2* hrow = (const ulonglong2*)h1dT[k];
                #pragma unroll
                for (int j=0;j<8;j++){
                    ulonglong2 hp = hrow[j];
                    ffma2(a01[2*j],   w.x, hp.x);
                    ffma2(a23[2*j],   w.y, hp.x);
                    ffma2(a01[2*j+1], w.x, hp.y);
                    ffma2(a23[2*j+1], w.y, hp.y);
                }
            }
        }
        __syncthreads();

        if (tid < 128){
            float hn_[NB];
            #pragma unroll
            for (int b=0;b<NB;b++){
                float2 g01 = unpack2(a01[b]);
                float2 g23 = unpack2(a23[b]);
                float rv  = res[b];
                float ir  = fmaf(rv, wi.x, bi.x);
                float iz  = fmaf(rv, wi.y, bi.y);
                float inn = fmaf(rv, wi.z, bi.z);
                float rg = sigf(ir + g01.x);
                float zg = sigf(iz + g01.y);
                float ng = tanhfast(fmaf(rg, g23.x, inn));
                float h1 = unpack2(h1dT[tid][b]).x;
                hn_[b] = fmaf(zg, h1 - ng, ng);
            }
            ulonglong2* myrow = (ulonglong2*)h1dT[tid];
            #pragma unroll
            for (int j=0;j<8;j++)
                myrow[j] = make_ulonglong2(pack2(hn_[2*j],hn_[2*j]), pack2(hn_[2*j+1],hn_[2*j+1]));
            #pragma unroll
            for (int bp=0;bp<8;bp++) h1p[tid][bp] = pack2(hn_[2*bp], hn_[2*bp+1]);
        }
        __syncthreads();

        if (tid < 150){
            u64 gi2[8], gh2[8];
            const u64 bi2 = pack2(g2bi, g2bi);
            const u64 bh2 = pack2(g2bh, g2bh);
            #pragma unroll
            for (int bp=0;bp<8;bp++){ gi2[bp] = bi2; gh2[bp] = bh2; }
            #pragma unroll 4
            for (int k=0;k<128;k++){
                float w = g_g2_wihT[k*160 + tid];
                u64 w2 = pack2(w, w);
                #pragma unroll
                for (int bp=0;bp<8;bp++) ffma2(gi2[bp], h1p[k][bp], w2);
            }
            #pragma unroll 2
            for (int k=0;k<50;k++){
                float w = g_g2_whhT[k*160 + tid];
                u64 w2 = pack2(w, w);
                #pragma unroll
                for (int bp=0;bp<8;bp++) ffma2(gh2[bp], h2p[k][bp], w2);
            }
            if (tid < 100){
                #pragma unroll
                for (int bp=0;bp<8;bp++){
                    float2 a = unpack2(gi2[bp]);
                    float2 b = unpack2(gh2[bp]);
                    s_rz[2*bp][tid]   = a.x + b.x;
                    s_rz[2*bp+1][tid] = a.y + b.y;
                }
            } else {
                int n = tid - 100;
                #pragma unroll
                for (int bp=0;bp<8;bp++){
                    float2 a = unpack2(gi2[bp]);
                    float2 b = unpack2(gh2[bp]);
                    s_in[2*bp][n]   = a.x;  s_hn[2*bp][n]   = b.x;
                    s_in[2*bp+1][n] = a.y;  s_hn[2*bp+1][n] = b.y;
                }
            }
        }
        __syncthreads();

        if (tid < 50){
            float h2n[NB];
            #pragma unroll
            for (int b=0;b<NB;b++){
                float rg = sigf(s_rz[b][tid]);
                float zg = sigf(s_rz[b][50+tid]);
                float ng = tanhfast(fmaf(rg, s_hn[b][tid], s_in[b][tid]));
                float h2 = h2s[b][tid];
                h2n[b] = fmaf(zg, h2 - ng, ng);
                h2s[b][tid] = h2n[b];
            }
            #pragma unroll
            for (int bp=0;bp<8;bp++) h2p[tid][bp] = pack2(h2n[2*bp], h2n[2*bp+1]);
        }
        __syncthreads();

        if (tid < NB){
            float s = decb;
            #pragma unroll 2
            for (int k=0;k<50;k++) s = fmaf(h2s[tid][k], dw[k], s);
            float r = sigf(s);
            res[tid] = r;
            out[(b0+tid)*T_SZ + t] = r;
        }
        __syncthreads();
    }
}

extern "C" void kernel_launch(void* const* d_in, const int* in_sizes, int n_in,
                              void* d_out, int out_size)
{
    const int*   node_data = (const int*)  d_in[0];
    const float* edge_data = (const float*)d_in[1];
    const float* emb       = (const float*)d_in[2];
    const float* l1_wih_f  = (const float*)d_in[3];
    const float* l1_whh_f  = (const float*)d_in[4];
    const float* l1_b_f    = (const float*)d_in[5];
    const float* l1_wih_b  = (const float*)d_in[6];
    const float* l1_whh_b  = (const float*)d_in[7];
    const float* l1_b_b    = (const float*)d_in[8];
    const float* l2_wih_f  = (const float*)d_in[9];
    const float* l2_whh_f  = (const float*)d_in[10];
    const float* l2_b_f    = (const float*)d_in[11];
    const float* l2_wih_b  = (const float*)d_in[12];
    const float* l2_whh_b  = (const float*)d_in[13];
    const float* l2_b_b    = (const float*)d_in[14];
    const float* fc1_w     = (const float*)d_in[15];
    const float* fc1_b     = (const float*)d_in[16];
    const float* fc2_w     = (const float*)d_in[17];
    const float* fc2_b     = (const float*)d_in[18];
    const float* g1_wih    = (const float*)d_in[19];
    const float* g1_whh    = (const float*)d_in[20];
    const float* g1_bih    = (const float*)d_in[21];
    const float* g1_bhh    = (const float*)d_in[22];
    const float* g2_wih    = (const float*)d_in[23];
    const float* g2_whh    = (const float*)d_in[24];
    const float* g2_bih    = (const float*)d_in[25];
    const float* g2_bhh    = (const float*)d_in[26];
    const float* dec_w     = (const float*)d_in[27];
    const float* dec_b     = (const float*)d_in[28];
    float* out = (float*)d_out;

    static int smem_set = 0;
    if (!smem_set){
        cudaFuncSetAttribute(k_lstm1, cudaFuncAttributeMaxDynamicSharedMemorySize, 109056);
        cudaFuncSetAttribute(k_lstm2, cudaFuncAttributeMaxDynamicSharedMemorySize, 83456);
        smem_set = 1;
    }

    k_prep<<<256, 256>>>(l1_wih_f, l1_whh_f, l1_b_f, l1_wih_b, l1_whh_b, l1_b_b,
                         l2_wih_f, l2_whh_f, l2_b_f, l2_wih_b, l2_whh_b, l2_b_b,
                         fc1_w, fc2_w, g1_wih, g1_whh, g1_bih, g1_bhh,
                         g2_wih, g2_whh);
    k_lstm1<<<dim3(B_SZ/32, 2), 256, 109056>>>(edge_data);
    k_proj<<<dim3((T_SZ*B_SZ)/128, 4, 2), 256>>>();
    k_lstm2<<<dim3(B_SZ/32, 2), 256, 83456>>>();
    k_fc<<<B_SZ, 256>>>(node_data, emb, fc1_b, fc2_b);
    k_dec<<<B_SZ/NB, 160>>>(edge_data, g2_bih, g2_bhh, dec_w, dec_b, out);
}

// round 15
// speedup vs baseline: 2.4464x; 1.5670x over previous
#include <cuda_runtime.h>
#include <math.h>
#include <stdint.h>

#define B_SZ 2048
#define T_SZ 200

typedef unsigned long long u64;

// ---- fast activations ----
__device__ __forceinline__ float fex2(float x){ float r; asm("ex2.approx.f32 %0, %1;" : "=f"(r) : "f"(x)); return r; }
__device__ __forceinline__ float frcp(float x){ float r; asm("rcp.approx.f32 %0, %1;" : "=f"(r) : "f"(x)); return r; }
#define LOG2E 1.4426950408889634f
__device__ __forceinline__ float sigf(float x){
    return frcp(1.0f + fex2(-LOG2E*x));
}
__device__ __forceinline__ float tanhfast(float x){
    float t = fminf(2.0f*LOG2E*x, 126.0f);
    float e = fex2(t);
    return (e - 1.0f) * frcp(e + 1.0f);
}
__device__ __forceinline__ uint32_t f2tf32(float x){
    uint32_t r; asm("cvt.rna.tf32.f32 %0, %1;" : "=r"(r) : "f"(x)); return r;
}

// ---------------- device scratch ----------------
__device__ __align__(16) float g_l1_whhF[2][65536];   // frag-linear tf32 recurrent weights
__device__ __align__(16) float g_l2_whhF[2][65536];
__device__ __align__(16) float g_l1_wih [2][512];
__device__ __align__(16) float g_l1_b   [2][512];
__device__ __align__(16) float g_l2_wihT[2][256*512];
__device__ __align__(16) float g_l2_b   [2][512];
__device__ __align__(16) float g_fc1_wT[256*256];
__device__ __align__(16) float g_fc2_wT[256*64];
__device__ __align__(16) float g_g1F[65536];          // GRU1 Whh frag-linear (quad r,z,n,0)
__device__ __align__(16) float g_g2F[49152];          // GRU2 combined [r|z|inn|hn] frag-linear, K=192, N=256
__device__ __align__(16) float g_g1_wih[512];
__device__ __align__(16) float g_g1_bih[512];
__device__ __align__(16) float g_g1_bhh[512];
__device__ __align__(16) float g_h1out[(size_t)T_SZ*B_SZ*256];      // [t][b][256]
__device__ __align__(16) float g_preact[2][(size_t)T_SZ*B_SZ*512];  // [dir][t*B+b][512]
__device__ __align__(16) float g_hn[4][B_SZ*128];
__device__ __align__(16) float g_hidden[B_SZ*128];

// ---------------- weight permutation ----------------
__global__ void k_prep(
    const float* __restrict__ l1_wih_f, const float* __restrict__ l1_whh_f, const float* __restrict__ l1_b_f,
    const float* __restrict__ l1_wih_b, const float* __restrict__ l1_whh_b, const float* __restrict__ l1_b_b,
    const float* __restrict__ l2_wih_f, const float* __restrict__ l2_whh_f, const float* __restrict__ l2_b_f,
    const float* __restrict__ l2_wih_b, const float* __restrict__ l2_whh_b, const float* __restrict__ l2_b_b,
    const float* __restrict__ fc1_w, const float* __restrict__ fc2_w,
    const float* __restrict__ g1_wih, const float* __restrict__ g1_whh,
    const float* __restrict__ g1_bih, const float* __restrict__ g1_bhh,
    const float* __restrict__ g2_wih, const float* __restrict__ g2_whh)
{
    const int idx = blockIdx.x*blockDim.x + threadIdx.x;
    const int stride = gridDim.x*blockDim.x;

    for (int i=idx; i<2*65536; i+=stride){            // L1/L2 frag-linear recurrent weights
        int dir = i>>16, x = i&65535;
        int r = x&1, lane = (x>>1)&31, j = (x>>6)&7, kt = (x>>9)&15, w = (x>>13)&7;
        int g = lane>>2, tg = lane&3;
        int k = kt*8 + tg + 4*r;
        int col = w*64 + j*8 + g;
        int srow = (col&3)*128 + (col>>2);
        const float* s1 = dir ? l1_whh_b : l1_whh_f;
        const float* s2 = dir ? l2_whh_b : l2_whh_f;
        g_l1_whhF[dir][x] = __uint_as_float(f2tf32(s1[srow*128 + k]));
        g_l2_whhF[dir][x] = __uint_as_float(f2tf32(s2[srow*128 + k]));
    }
    for (int i=idx; i<65536; i+=stride){              // GRU1 Whh frag-linear, quad (r,z,n,0)
        int x = i;
        int r = x&1, lane = (x>>1)&31, j = (x>>6)&7, kt = (x>>9)&15, w = (x>>13)&7;
        int g = lane>>2, tg = lane&3;
        int k = kt*8 + tg + 4*r;
        int col = w*64 + j*8 + g;
        int h = col>>2, q = col&3;
        float v = (q<3) ? g1_whh[(q*128+h)*128 + k] : 0.0f;
        g_g1F[x] = __uint_as_float(f2tf32(v));
    }
    for (int i=idx; i<49152; i+=stride){              // GRU2 combined frag-linear
        int x = i;
        int r = x&1, lane = (x>>1)&31, j = (x>>6)&7;
        int rem = x>>9;                 // 0..95
        int kt = rem % 24, w = rem / 24;
        int g = lane>>2, tg = lane&3;
        int k = kt*8 + tg + 4*r;        // 0..191
        int col = w*64 + j*8 + g;       // 0..255
        float v = 0.0f;
        if (col < 100){                 // r/z: Wih + Whh combined
            if (k < 128)            v = g2_wih[col*128 + k];
            else if (k < 178)       v = g2_whh[col*50 + (k-128)];
        } else if (col < 150){          // inn: Wih only
            if (k < 128)            v = g2_wih[col*128 + k];
        } else if (col < 200){          // hn: Whh only
            if (k >= 128 && k < 178) v = g2_whh[(col-50)*50 + (k-128)];
        }
        g_g2F[x] = __uint_as_float(f2tf32(v));
    }
    for (int i=idx; i<2*256*512; i+=stride){          // L2 wih^T (for k_proj)
        int dir=i>>17, r=i&131071, k=r>>9, col=r&511, h=col>>2, q=col&3;
        const float* s = dir ? l2_wih_b : l2_wih_f;
        g_l2_wihT[dir][r] = s[(q*128+h)*256 + k];
    }
    for (int i=idx; i<2*512; i+=stride){
        int dir=i>>9, col=i&511, h=col>>2, q=col&3, g=q*128+h;
        g_l1_wih[dir][col] = (dir ? l1_wih_b : l1_wih_f)[g];
        g_l1_b  [dir][col] = (dir ? l1_b_b   : l1_b_f  )[g];
        g_l2_b  [dir][col] = (dir ? l2_b_b   : l2_b_f  )[g];
    }
    for (int i=idx; i<256*256; i+=stride){
        int c=i>>8, j=i&255;
        g_fc1_wT[i] = fc1_w[j*256+c];
    }
    for (int i=idx; i<256*64; i+=stride){
        int c=i>>6, j=i&63;
        g_fc2_wT[i] = fc2_w[j*256+c];
    }
    for (int i=idx; i<512; i+=stride){
        int h=i>>2, q=i&3;
        g_g1_wih[i] = (q<3) ? g1_wih[q*128+h] : 0.0f;
        g_g1_bih[i] = (q<3) ? g1_bih[q*128+h] : 0.0f;
        g_g1_bhh[i] = (q<3) ? g1_bhh[q*128+h] : 0.0f;
    }
}

// ---------------- BiLSTM layer 1: tensor-core scan (unchanged, proven) ----------------
__global__ void __launch_bounds__(256) k_lstm1(const float* __restrict__ edge)
{
    extern __shared__ char smem[];
    uint32_t* sA = (uint32_t*)smem;
    float*    sG = (float*)(smem + 16896);
    float*    sx = (float*)(smem + 83456);

    const int dir = blockIdx.y;
    const int b0  = blockIdx.x * 32;
    const int tid = threadIdx.x;
    const int wid = tid >> 5, lane = tid & 31;
    const int g   = lane >> 2, tg = lane & 3;
    const int hh  = tid & 127, half = tid >> 7;

    for (int i=tid; i<32*T_SZ; i+=256){
        int b = i / T_SZ, t = i % T_SZ;
        sx[b*T_SZ + t] = edge[(b0+b)*T_SZ + t];
    }
    for (int i=tid; i<32*132; i+=256) sA[i] = 0u;

    float c[16];
    #pragma unroll
    for (int q=0;q<16;q++) c[q] = 0.0f;

    const float4 wi = ((const float4*)g_l1_wih[dir])[hh];
    const float4 bb = ((const float4*)g_l1_b[dir])[hh];
    const u64* __restrict__ WF = (const u64*)g_l1_whhF[dir];
    __syncthreads();

    for (int s=0; s<T_SZ; s++){
        const int t = dir ? (T_SZ-1-s) : s;

        float acc[2][8][4];
        #pragma unroll
        for (int mi=0;mi<2;mi++)
            #pragma unroll
            for (int j=0;j<8;j++)
                #pragma unroll
                for (int q=0;q<4;q++) acc[mi][j][q] = 0.0f;

        #pragma unroll
        for (int kt=0;kt<16;kt++){
            uint32_t a[2][4];
            #pragma unroll
            for (int mi=0;mi<2;mi++){
                int rr = mi*16 + g;
                a[mi][0] = sA[rr*132     + kt*8 + tg];
                a[mi][1] = sA[(rr+8)*132 + kt*8 + tg];
                a[mi][2] = sA[rr*132     + kt*8 + tg + 4];
                a[mi][3] = sA[(rr+8)*132 + kt*8 + tg + 4];
            }
            #pragma unroll
            for (int j=0;j<8;j++){
                u64 wv = WF[((wid*16 + kt)*8 + j)*32 + lane];
                uint32_t bw0 = (uint32_t)wv, bw1 = (uint32_t)(wv>>32);
                #pragma unroll
                for (int mi=0;mi<2;mi++){
                    asm("mma.sync.aligned.m16n8k8.row.col.f32.tf32.tf32.f32 "
                        "{%0,%1,%2,%3}, {%4,%5,%6,%7}, {%8,%9}, {%0,%1,%2,%3};"
                        : "+f"(acc[mi][j][0]), "+f"(acc[mi][j][1]),
                          "+f"(acc[mi][j][2]), "+f"(acc[mi][j][3])
                        : "r"(a[mi][0]), "r"(a[mi][1]), "r"(a[mi][2]), "r"(a[mi][3]),
                          "r"(bw0), "r"(bw1));
                }
            }
        }
        #pragma unroll
        for (int mi=0;mi<2;mi++){
            #pragma unroll
            for (int j=0;j<8;j++){
                int row = mi*16 + g, colb = wid*64 + j*8 + 2*tg;
                *(float2*)&sG[row*520 + colb]     = make_float2(acc[mi][j][0], acc[mi][j][1]);
                *(float2*)&sG[(row+8)*520 + colb] = make_float2(acc[mi][j][2], acc[mi][j][3]);
            }
        }
        __syncthreads();

        float* outp = g_h1out + (size_t)t*(B_SZ*256) + (size_t)(b0 + half*16)*256 + dir*128 + hh;
        #pragma unroll
        for (int q=0;q<16;q++){
            int b = half*16 + q;
            float4 gt = *(float4*)&sG[b*520 + 4*hh];
            float xv = sx[b*T_SZ + t];
            float gi = fmaf(wi.x, xv, gt.x + bb.x);
            float gf = fmaf(wi.y, xv, gt.y + bb.y);
            float gg = fmaf(wi.z, xv, gt.z + bb.z);
            float go = fmaf(wi.w, xv, gt.w + bb.w);
            float ig = sigf(gi), fg = sigf(gf), cg = tanhfast(gg), og = sigf(go);
            c[q] = fmaf(fg, c[q], ig*cg);
            float h = og * tanhfast(c[q]);
            sA[b*132 + hh] = f2tf32(h);
            outp[q*256] = h;
            if (s == T_SZ-1) g_hn[dir][(b0+b)*128 + hh] = h;
        }
        __syncthreads();
    }
}

// ---------------- L2 input projection: tf32 tensor-core GEMM (unchanged, proven) ----------------
__global__ void __launch_bounds__(256) k_proj()
{
    const int dir = blockIdx.z;
    const int c0  = blockIdx.y * 128;
    const size_t r0 = (size_t)blockIdx.x * 128;
    const int tid  = threadIdx.x;
    const int wid  = tid >> 5;
    const int lane = tid & 31;
    const int wm = wid >> 2;
    const int wn = wid & 3;
    const int g  = lane >> 2;
    const int tg = lane & 3;

    __shared__ float sA[128][36];
    __shared__ float sB[32][136];

    float acc[4][4][4];
    #pragma unroll
    for (int i=0;i<4;i++)
        #pragma unroll
        for (int j=0;j<4;j++)
            #pragma unroll
            for (int q=0;q<4;q++) acc[i][j][q] = 0.0f;

    const int arow = tid >> 1;
    const int acol = (tid & 1) * 16;
    const int brow = tid >> 3;
    const int bcol = (tid & 7) * 16;
    const float* __restrict__ Asrc = g_h1out + (r0 + arow)*256 + acol;
    const float* __restrict__ Bsrc = g_l2_wihT[dir] + (size_t)brow*512 + c0 + bcol;

    for (int ks=0; ks<256; ks+=32){
        __syncthreads();
        #pragma unroll
        for (int v=0; v<4; v++){
            float4 a = *(const float4*)(Asrc + ks + v*4);
            uint4 ua = make_uint4(f2tf32(a.x), f2tf32(a.y), f2tf32(a.z), f2tf32(a.w));
            *(uint4*)&sA[arow][acol + v*4] = ua;
        }
        #pragma unroll
        for (int v=0; v<4; v++){
            float4 b = *(const float4*)(Bsrc + (size_t)ks*512 + v*4);
            uint4 ub = make_uint4(f2tf32(b.x), f2tf32(b.y), f2tf32(b.z), f2tf32(b.w));
            *(uint4*)&sB[brow][bcol + v*4] = ub;
        }
        __syncthreads();

        #pragma unroll
        for (int kt=0; kt<4; kt++){
            uint32_t bf[4][2];
            #pragma unroll
            for (int j=0;j<4;j++){
                int col = wn*32 + j*8 + g;
                bf[j][0] = *(const uint32_t*)&sB[kt*8 + tg    ][col];
                bf[j][1] = *(const uint32_t*)&sB[kt*8 + tg + 4][col];
            }
            #pragma unroll
            for (int i=0;i<4;i++){
                int r = wm*64 + i*16;
                uint32_t a0 = *(const uint32_t*)&sA[r + g    ][kt*8 + tg    ];
                uint32_t a1 = *(const uint32_t*)&sA[r + g + 8][kt*8 + tg    ];
                uint32_t a2 = *(const uint32_t*)&sA[r + g    ][kt*8 + tg + 4];
                uint32_t a3 = *(const uint32_t*)&sA[r + g + 8][kt*8 + tg + 4];
                #pragma unroll
                for (int j=0;j<4;j++){
                    asm("mma.sync.aligned.m16n8k8.row.col.f32.tf32.tf32.f32 "
                        "{%0,%1,%2,%3}, {%4,%5,%6,%7}, {%8,%9}, {%0,%1,%2,%3};"
                        : "+f"(acc[i][j][0]), "+f"(acc[i][j][1]),
                          "+f"(acc[i][j][2]), "+f"(acc[i][j][3])
                        : "r"(a0), "r"(a1), "r"(a2), "r"(a3),
                          "r"(bf[j][0]), "r"(bf[j][1]));
                }
            }
        }
    }

    float* __restrict__ C = g_preact[dir];
    #pragma unroll
    for (int j=0;j<4;j++){
        int col = c0 + wn*32 + j*8 + 2*tg;
        float2 bias = *(const float2*)&g_l2_b[dir][col];
        #pragma unroll
        for (int i=0;i<4;i++){
            size_t rA = r0 + wm*64 + i*16 + g;
            float2 v0 = make_float2(acc[i][j][0]+bias.x, acc[i][j][1]+bias.y);
            float2 v1 = make_float2(acc[i][j][2]+bias.x, acc[i][j][3]+bias.y);
            *(float2*)&C[rA*512 + col]     = v0;
            *(float2*)&C[(rA+8)*512 + col] = v1;
        }
    }
}

// ---------------- BiLSTM layer 2: tensor-core recurrent scan (unchanged, proven) ----------------
__global__ void __launch_bounds__(256) k_lstm2()
{
    extern __shared__ char smem[];
    uint32_t* sA = (uint32_t*)smem;
    float*    sG = (float*)(smem + 16896);

    const int dir = blockIdx.y;
    const int b0  = blockIdx.x * 32;
    const int tid = threadIdx.x;
    const int wid = tid >> 5, lane = tid & 31;
    const int g   = lane >> 2, tg = lane & 3;
    const int hh  = tid & 127, half = tid >> 7;

    for (int i=tid; i<32*132; i+=256) sA[i] = 0u;
    float c[16];
    #pragma unroll
    for (int q=0;q<16;q++) c[q] = 0.0f;

    const u64* __restrict__ WF = (const u64*)g_l2_whhF[dir];
    const float* __restrict__ pre = g_preact[dir];
    __syncthreads();

    for (int s=0; s<T_SZ; s++){
        const int t = dir ? (T_SZ-1-s) : s;

        float acc[2][8][4];
        #pragma unroll
        for (int mi=0;mi<2;mi++)
            #pragma unroll
            for (int j=0;j<8;j++)
                #pragma unroll
                for (int q=0;q<4;q++) acc[mi][j][q] = 0.0f;

        #pragma unroll
        for (int kt=0;kt<16;kt++){
            uint32_t a[2][4];
            #pragma unroll
            for (int mi=0;mi<2;mi++){
                int rr = mi*16 + g;
                a[mi][0] = sA[rr*132     + kt*8 + tg];
                a[mi][1] = sA[(rr+8)*132 + kt*8 + tg];
                a[mi][2] = sA[rr*132     + kt*8 + tg + 4];
                a[mi][3] = sA[(rr+8)*132 + kt*8 + tg + 4];
            }
            #pragma unroll
            for (int j=0;j<8;j++){
                u64 wv = WF[((wid*16 + kt)*8 + j)*32 + lane];
                uint32_t bw0 = (uint32_t)wv, bw1 = (uint32_t)(wv>>32);
                #pragma unroll
                for (int mi=0;mi<2;mi++){
                    asm("mma.sync.aligned.m16n8k8.row.col.f32.tf32.tf32.f32 "
                        "{%0,%1,%2,%3}, {%4,%5,%6,%7}, {%8,%9}, {%0,%1,%2,%3};"
                        : "+f"(acc[mi][j][0]), "+f"(acc[mi][j][1]),
                          "+f"(acc[mi][j][2]), "+f"(acc[mi][j][3])
                        : "r"(a[mi][0]), "r"(a[mi][1]), "r"(a[mi][2]), "r"(a[mi][3]),
                          "r"(bw0), "r"(bw1));
                }
            }
        }
        #pragma unroll
        for (int mi=0;mi<2;mi++){
            #pragma unroll
            for (int j=0;j<8;j++){
                int row = mi*16 + g, colb = wid*64 + j*8 + 2*tg;
                *(float2*)&sG[row*520 + colb]     = make_float2(acc[mi][j][0], acc[mi][j][1]);
                *(float2*)&sG[(row+8)*520 + colb] = make_float2(acc[mi][j][2], acc[mi][j][3]);
            }
        }
        __syncthreads();

        #pragma unroll 4
        for (int q=0;q<16;q++){
            int b = half*16 + q;
            float4 gt = *(float4*)&sG[b*520 + 4*hh];
            float4 p  = *(const float4*)&pre[((size_t)t*B_SZ + b0 + b)*512 + 4*hh];
            float ig = sigf(gt.x + p.x);
            float fg = sigf(gt.y + p.y);
            float cg = tanhfast(gt.z + p.z);
            float og = sigf(gt.w + p.w);
            c[q] = fmaf(fg, c[q], ig*cg);
            float h = og * tanhfast(c[q]);
            sA[b*132 + hh] = f2tf32(h);
            if (s == T_SZ-1) g_hn[2+dir][(b0+b)*128 + hh] = h;
        }
        __syncthreads();
    }
}

// ---------------- FC head ----------------
__global__ void __launch_bounds__(256) k_fc(const int* __restrict__ node_data,
                                            const float* __restrict__ emb,
                                            const float* __restrict__ fc1_b,
                                            const float* __restrict__ fc2_b)
{
    const int r = blockIdx.x;
    const int c = threadIdx.x;
    __shared__ float sh_in[256];
    __shared__ float sh_mid[256];

    int d = r >> 10;
    int b = ((r & 1023) << 1) + (c >> 7);
    int k = c & 127;
    sh_in[c] = g_hn[d][b*128 + k] + g_hn[2+d][b*128 + k];
    __syncthreads();

    float acc = fc1_b[c];
    #pragma unroll 4
    for (int i=0;i<256;i++) acc = fmaf(sh_in[i], g_fc1_wT[i*256 + c], acc);
    sh_mid[c] = sigf(acc);
    __syncthreads();

    if (c < 64){
        float a2 = fc2_b[c];
        #pragma unroll 4
        for (int i=0;i<256;i++) a2 = fmaf(sh_mid[i], g_fc2_wT[i*64 + c], a2);
        g_hidden[r*128 + c] = sigf(a2);
    } else if (c < 128){
        int e = c - 64;
        int n0 = node_data[r*2], n1 = node_data[r*2+1];
        g_hidden[r*128 + 64 + e] = 0.5f*(emb[n0*64 + e] + emb[n1*64 + e]);
    }
}

// ---------------- decoder: tensor-core GRU scans, 16 batch rows/CTA ----------------
// sA u32[16][196]: tf32 concat state [h1(128) | h2(50) | pad]. Stride 196 (196%32==4 -> frag-bijective).
// Phase A: gates = Whh1 @ h1, M=16 N=512 K=128 (8 warps).
// Phase B: [r|z|inn|hn] = Wcat @ [h1n|h2], M=16 N=256 K=192 (warps 0-3).
__global__ void __launch_bounds__(256) k_dec(const float* __restrict__ edge,
                                             const float* __restrict__ g2_bih,
                                             const float* __restrict__ g2_bhh,
                                             const float* __restrict__ dec_w,
                                             const float* __restrict__ dec_b,
                                             float* __restrict__ out)
{
    extern __shared__ char smem[];
    uint32_t* sA  = (uint32_t*)smem;               // [16][196]  12544 B
    float*    sG  = (float*)(smem + 12544);        // [16][520]  33280 B
    float*    sGB = (float*)(smem + 45824);        // [16][200]  12800 B
    float*    h2s = (float*)(smem + 58624);        // [16][52]    3328 B
    float*    res = (float*)(smem + 61952);        // [16]
    float*    dw  = (float*)(smem + 62016);        // [52]

    const int b0  = blockIdx.x * 16;
    const int tid = threadIdx.x;
    const int wid = tid >> 5, lane = tid & 31;
    const int g   = lane >> 2, tg = lane & 3;
    const int hh  = tid & 127, half = tid >> 7;    // epiA: (hh, batch-half)
    const int n2  = tid & 63;                      // epiC: gate idx
    const int half2 = (tid >> 6) & 1;
    const bool c_act = (tid < 128) && (n2 < 50);

    for (int i=tid; i<16*196; i+=256) sA[i] = 0u;
    if (tid < 52) dw[tid] = (tid < 50) ? dec_w[tid] : 0.0f;
    if (tid < 16) res[tid] = edge[(b0+tid)*T_SZ + (T_SZ-1)];
    __syncthreads();   // zero-init done before state stores

    float h1[8];
    #pragma unroll
    for (int q=0;q<8;q++){
        int b = half*8 + q;
        h1[q] = g_hidden[(b0+b)*128 + hh];
        sA[b*196 + hh] = f2tf32(h1[q]);
    }
    float h2[8];
    #pragma unroll
    for (int q=0;q<8;q++) h2[q] = 0.0f;
    if (c_act){
        #pragma unroll
        for (int q=0;q<8;q++) h2s[(half2*8+q)*52 + n2] = 0.0f;
    }

    const float4 wi = ((const float4*)g_g1_wih)[hh];
    const float4 bi = ((const float4*)g_g1_bih)[hh];
    const float4 bh = ((const float4*)g_g1_bhh)[hh];
    float bBr=0.f, bBz=0.f, bBi=0.f, bBh=0.f;
    if (c_act){
        bBr = g2_bih[n2]     + g2_bhh[n2];
        bBz = g2_bih[50+n2]  + g2_bhh[50+n2];
        bBi = g2_bih[100+n2];
        bBh = g2_bhh[100+n2];
    }
    const float decb = dec_b[0];
    const u64* __restrict__ WF1 = (const u64*)g_g1F;
    const u64* __restrict__ WF2 = (const u64*)g_g2F;
    __syncthreads();

    for (int t=0; t<T_SZ; t++){
        // ---- Phase A: GRU1 hidden matvec (all 8 warps) ----
        float acc[8][4];
        #pragma unroll
        for (int j=0;j<8;j++)
            #pragma unroll
            for (int q=0;q<4;q++) acc[j][q] = 0.0f;
        #pragma unroll
        for (int kt=0;kt<16;kt++){
            uint32_t a0 = sA[g*196     + kt*8 + tg];
            uint32_t a1 = sA[(g+8)*196 + kt*8 + tg];
            uint32_t a2 = sA[g*196     + kt*8 + tg + 4];
            uint32_t a3 = sA[(g+8)*196 + kt*8 + tg + 4];
            #pragma unroll
            for (int j=0;j<8;j++){
                u64 wv = WF1[((wid*16 + kt)*8 + j)*32 + lane];
                uint32_t bw0 = (uint32_t)wv, bw1 = (uint32_t)(wv>>32);
                asm("mma.sync.aligned.m16n8k8.row.col.f32.tf32.tf32.f32 "
                    "{%0,%1,%2,%3}, {%4,%5,%6,%7}, {%8,%9}, {%0,%1,%2,%3};"
                    : "+f"(acc[j][0]), "+f"(acc[j][1]), "+f"(acc[j][2]), "+f"(acc[j][3])
                    : "r"(a0), "r"(a1), "r"(a2), "r"(a3), "r"(bw0), "r"(bw1));
            }
        }
        #pragma unroll
        for (int j=0;j<8;j++){
            int colb = wid*64 + j*8 + 2*tg;
            *(float2*)&sG[g*520 + colb]     = make_float2(acc[j][0], acc[j][1]);
            *(float2*)&sG[(g+8)*520 + colb] = make_float2(acc[j][2], acc[j][3]);
        }
        __syncthreads();

        // ---- EpiA: GRU1 combine (all 256 threads, 8 rows each) ----
        #pragma unroll
        for (int q=0;q<8;q++){
            int b = half*8 + q;
            float4 gt = *(float4*)&sG[b*520 + 4*hh];
            float rv = res[b];
            float rg = sigf( fmaf(wi.x, rv, bi.x) + gt.x + bh.x );
            float zg = sigf( fmaf(wi.y, rv, bi.y) + gt.y + bh.y );
            float ng = tanhfast( fmaf(wi.z, rv, bi.z) + rg*(gt.z + bh.z) );
            h1[q] = fmaf(zg, h1[q] - ng, ng);
            sA[b*196 + hh] = f2tf32(h1[q]);
        }
        __syncthreads();

        // ---- Phase B: GRU2 [r|z|inn|hn] over [h1n|h2] (warps 0-3) ----
        if (wid < 4){
            float ac2[8][4];
            #pragma unroll
            for (int j=0;j<8;j++)
                #pragma unroll
                for (int q=0;q<4;q++) ac2[j][q] = 0.0f;
            #pragma unroll
            for (int kt=0;kt<24;kt++){
                uint32_t a0 = sA[g*196     + kt*8 + tg];
                uint32_t a1 = sA[(g+8)*196 + kt*8 + tg];
                uint32_t a2 = sA[g*196     + kt*8 + tg + 4];
                uint32_t a3 = sA[(g+8)*196 + kt*8 + tg + 4];
                #pragma unroll
                for (int j=0;j<8;j++){
                    u64 wv = WF2[((wid*24 + kt)*8 + j)*32 + lane];
                    uint32_t bw0 = (uint32_t)wv, bw1 = (uint32_t)(wv>>32);
                    asm("mma.sync.aligned.m16n8k8.row.col.f32.tf32.tf32.f32 "
                        "{%0,%1,%2,%3}, {%4,%5,%6,%7}, {%8,%9}, {%0,%1,%2,%3};"
                        : "+f"(ac2[j][0]), "+f"(ac2[j][1]), "+f"(ac2[j][2]), "+f"(ac2[j][3])
                        : "r"(a0), "r"(a1), "r"(a2), "r"(a3), "r"(bw0), "r"(bw1));
                }
            }
            #pragma unroll
            for (int j=0;j<8;j++){
                int colb = wid*64 + j*8 + 2*tg;
                *(float2*)&sGB[g*200 + colb]     = make_float2(ac2[j][0], ac2[j][1]);
                *(float2*)&sGB[(g+8)*200 + colb] = make_float2(ac2[j][2], ac2[j][3]);
            }
        }
        __syncthreads();

        // ---- EpiC: GRU2 combine (100 threads, 8 rows each) ----
        if (c_act){
            #pragma unroll
            for (int q=0;q<8;q++){
                int b = half2*8 + q;
                float r2 = sigf(sGB[b*200 + n2]      + bBr);
                float z2 = sigf(sGB[b*200 + 50 + n2] + bBz);
                float nn = tanhfast( (sGB[b*200 + 100 + n2] + bBi) + r2*(sGB[b*200 + 150 + n2] + bBh) );
                h2[q] = fmaf(z2, h2[q] - nn, nn);
                sA[b*196 + 128 + n2] = f2tf32(h2[q]);
                h2s[b*52 + n2] = h2[q];
            }
        }
        __syncthreads();

        // ---- Phase D: decoder dot + sigmoid (16 threads) ----
        if (tid < 16){
            float s = decb;
            #pragma unroll 2
            for (int k=0;k<50;k++) s = fmaf(h2s[tid*52 + k], dw[k], s);
            float r = sigf(s);
            res[tid] = r;
            out[(b0+tid)*T_SZ + t] = r;
        }
        __syncthreads();
    }
}

extern "C" void kernel_launch(void* const* d_in, const int* in_sizes, int n_in,
                              void* d_out, int out_size)
{
    const int*   node_data = (const int*)  d_in[0];
    const float* edge_data = (const float*)d_in[1];
    const float* emb       = (const float*)d_in[2];
    const float* l1_wih_f  = (const float*)d_in[3];
    const float* l1_whh_f  = (const float*)d_in[4];
    const float* l1_b_f    = (const float*)d_in[5];
    const float* l1_wih_b  = (const float*)d_in[6];
    const float* l1_whh_b  = (const float*)d_in[7];
    const float* l1_b_b    = (const float*)d_in[8];
    const float* l2_wih_f  = (const float*)d_in[9];
    const float* l2_whh_f  = (const float*)d_in[10];
    const float* l2_b_f    = (const float*)d_in[11];
    const float* l2_wih_b  = (const float*)d_in[12];
    const float* l2_whh_b  = (const float*)d_in[13];
    const float* l2_b_b    = (const float*)d_in[14];
    const float* fc1_w     = (const float*)d_in[15];
    const float* fc1_b     = (const float*)d_in[16];
    const float* fc2_w     = (const float*)d_in[17];
    const float* fc2_b     = (const float*)d_in[18];
    const float* g1_wih    = (const float*)d_in[19];
    const float* g1_whh    = (const float*)d_in[20];
    const float* g1_bih    = (const float*)d_in[21];
    const float* g1_bhh    = (const float*)d_in[22];
    const float* g2_wih    = (const float*)d_in[23];
    const float* g2_whh    = (const float*)d_in[24];
    const float* g2_bih    = (const float*)d_in[25];
    const float* g2_bhh    = (const float*)d_in[26];
    const float* dec_w     = (const float*)d_in[27];
    const float* dec_b     = (const float*)d_in[28];
    float* out = (float*)d_out;

    static int smem_set = 0;
    if (!smem_set){
        cudaFuncSetAttribute(k_lstm1, cudaFuncAttributeMaxDynamicSharedMemorySize, 109056);
        cudaFuncSetAttribute(k_lstm2, cudaFuncAttributeMaxDynamicSharedMemorySize, 83456);
        cudaFuncSetAttribute(k_dec,   cudaFuncAttributeMaxDynamicSharedMemorySize, 62464);
        smem_set = 1;
    }

    k_prep<<<256, 256>>>(l1_wih_f, l1_whh_f, l1_b_f, l1_wih_b, l1_whh_b, l1_b_b,
                         l2_wih_f, l2_whh_f, l2_b_f, l2_wih_b, l2_whh_b, l2_b_b,
                         fc1_w, fc2_w, g1_wih, g1_whh, g1_bih, g1_bhh,
                         g2_wih, g2_whh);
    k_lstm1<<<dim3(B_SZ/32, 2), 256, 109056>>>(edge_data);
    k_proj<<<dim3((T_SZ*B_SZ)/128, 4, 2), 256>>>();
    k_lstm2<<<dim3(B_SZ/32, 2), 256, 83456>>>();
    k_fc<<<B_SZ, 256>>>(node_data, emb, fc1_b, fc2_b);
    k_dec<<<B_SZ/16, 256, 62464>>>(edge_data, g2_bih, g2_bhh, dec_w, dec_b, out);
}

// round 16
// speedup vs baseline: 3.2241x; 1.3179x over previous
#include <cuda_runtime.h>
#include <math.h>
#include <stdint.h>

#define B_SZ 2048
#define T_SZ 200

typedef unsigned long long u64;

// ---- fast activations ----
__device__ __forceinline__ float fex2(float x){ float r; asm("ex2.approx.f32 %0, %1;" : "=f"(r) : "f"(x)); return r; }
__device__ __forceinline__ float frcp(float x){ float r; asm("rcp.approx.f32 %0, %1;" : "=f"(r) : "f"(x)); return r; }
#define LOG2E 1.4426950408889634f
__device__ __forceinline__ float sigf(float x){
    return frcp(1.0f + fex2(-LOG2E*x));
}
__device__ __forceinline__ float tanhfast(float x){
    float t = fminf(2.0f*LOG2E*x, 126.0f);
    float e = fex2(t);
    return (e - 1.0f) * frcp(e + 1.0f);
}
__device__ __forceinline__ uint32_t f2tf32(float x){
    uint32_t r; asm("cvt.rna.tf32.f32 %0, %1;" : "=r"(r) : "f"(x)); return r;
}

// ---------------- device scratch ----------------
__device__ __align__(16) float g_l1_whhF[2][65536];   // frag-linear tf32 recurrent weights
__device__ __align__(16) float g_l2_whhF[2][65536];
__device__ __align__(16) float g_l1_wih [2][512];
__device__ __align__(16) float g_l1_b   [2][512];
__device__ __align__(16) float g_l2_wihT[2][256*512];
__device__ __align__(16) float g_l2_b   [2][512];
__device__ __align__(16) float g_fc1_wT[256*256];
__device__ __align__(16) float g_fc2_wT[256*64];
__device__ __align__(16) float g_g1F[65536];          // GRU1 Whh frag-linear (quad r,z,n,0)
__device__ __align__(16) float g_g2F[49152];          // GRU2 combined [r|z|inn|hn] frag-linear
__device__ __align__(16) float g_g1_wih[512];
__device__ __align__(16) float g_g1_bih[512];
__device__ __align__(16) float g_g1_bhh[512];
__device__ __align__(16) float g_h1out[(size_t)T_SZ*B_SZ*256];      // [t][b][256]
__device__ __align__(16) float g_preact[2][(size_t)T_SZ*B_SZ*512];  // [dir][t*B+b][512]
__device__ __align__(16) float g_hn[4][B_SZ*128];
__device__ __align__(16) float g_hidden[B_SZ*128];

// ---------------- weight permutation ----------------
__global__ void k_prep(
    const float* __restrict__ l1_wih_f, const float* __restrict__ l1_whh_f, const float* __restrict__ l1_b_f,
    const float* __restrict__ l1_wih_b, const float* __restrict__ l1_whh_b, const float* __restrict__ l1_b_b,
    const float* __restrict__ l2_wih_f, const float* __restrict__ l2_whh_f, const float* __restrict__ l2_b_f,
    const float* __restrict__ l2_wih_b, const float* __restrict__ l2_whh_b, const float* __restrict__ l2_b_b,
    const float* __restrict__ fc1_w, const float* __restrict__ fc2_w,
    const float* __restrict__ g1_wih, const float* __restrict__ g1_whh,
    const float* __restrict__ g1_bih, const float* __restrict__ g1_bhh,
    const float* __restrict__ g2_wih, const float* __restrict__ g2_whh)
{
    const int idx = blockIdx.x*blockDim.x + threadIdx.x;
    const int stride = gridDim.x*blockDim.x;

    for (int i=idx; i<2*65536; i+=stride){            // L1/L2 frag-linear recurrent weights
        int dir = i>>16, x = i&65535;
        int r = x&1, lane = (x>>1)&31, j = (x>>6)&7, kt = (x>>9)&15, w = (x>>13)&7;
        int g = lane>>2, tg = lane&3;
        int k = kt*8 + tg + 4*r;
        int col = w*64 + j*8 + g;
        int srow = (col&3)*128 + (col>>2);
        const float* s1 = dir ? l1_whh_b : l1_whh_f;
        const float* s2 = dir ? l2_whh_b : l2_whh_f;
        g_l1_whhF[dir][x] = __uint_as_float(f2tf32(s1[srow*128 + k]));
        g_l2_whhF[dir][x] = __uint_as_float(f2tf32(s2[srow*128 + k]));
    }
    for (int i=idx; i<65536; i+=stride){              // GRU1 Whh frag-linear, quad (r,z,n,0)
        int x = i;
        int r = x&1, lane = (x>>1)&31, j = (x>>6)&7, kt = (x>>9)&15, w = (x>>13)&7;
        int g = lane>>2, tg = lane&3;
        int k = kt*8 + tg + 4*r;
        int col = w*64 + j*8 + g;
        int h = col>>2, q = col&3;
        float v = (q<3) ? g1_whh[(q*128+h)*128 + k] : 0.0f;
        g_g1F[x] = __uint_as_float(f2tf32(v));
    }
    for (int i=idx; i<49152; i+=stride){              // GRU2 combined frag-linear
        int x = i;
        int r = x&1, lane = (x>>1)&31, j = (x>>6)&7;
        int rem = x>>9;                 // 0..95
        int kt = rem % 24, w = rem / 24;
        int g = lane>>2, tg = lane&3;
        int k = kt*8 + tg + 4*r;        // 0..191
        int col = w*64 + j*8 + g;       // 0..255
        float v = 0.0f;
        if (col < 100){                 // r/z: Wih + Whh combined
            if (k < 128)            v = g2_wih[col*128 + k];
            else if (k < 178)       v = g2_whh[col*50 + (k-128)];
        } else if (col < 150){          // inn: Wih only
            if (k < 128)            v = g2_wih[col*128 + k];
        } else if (col < 200){          // hn: Whh only
            if (k >= 128 && k < 178) v = g2_whh[(col-50)*50 + (k-128)];
        }
        g_g2F[x] = __uint_as_float(f2tf32(v));
    }
    for (int i=idx; i<2*256*512; i+=stride){          // L2 wih^T (for k_proj)
        int dir=i>>17, r=i&131071, k=r>>9, col=r&511, h=col>>2, q=col&3;
        const float* s = dir ? l2_wih_b : l2_wih_f;
        g_l2_wihT[dir][r] = s[(q*128+h)*256 + k];
    }
    for (int i=idx; i<2*512; i+=stride){
        int dir=i>>9, col=i&511, h=col>>2, q=col&3, g=q*128+h;
        g_l1_wih[dir][col] = (dir ? l1_wih_b : l1_wih_f)[g];
        g_l1_b  [dir][col] = (dir ? l1_b_b   : l1_b_f  )[g];
        g_l2_b  [dir][col] = (dir ? l2_b_b   : l2_b_f  )[g];
    }
    for (int i=idx; i<256*256; i+=stride){
        int c=i>>8, j=i&255;
        g_fc1_wT[i] = fc1_w[j*256+c];
    }
    for (int i=idx; i<256*64; i+=stride){
        int c=i>>6, j=i&63;
        g_fc2_wT[i] = fc2_w[j*256+c];
    }
    for (int i=idx; i<512; i+=stride){
        int h=i>>2, q=i&3;
        g_g1_wih[i] = (q<3) ? g1_wih[q*128+h] : 0.0f;
        g_g1_bih[i] = (q<3) ? g1_bih[q*128+h] : 0.0f;
        g_g1_bhh[i] = (q<3) ? g1_bhh[q*128+h] : 0.0f;
    }
}

// ---------------- BiLSTM layer 1: tensor-core scan, 16 batch rows/CTA, 2 CTAs/SM ----------------
// smem: sA u32[16][132] | sG float[16][520] | sx float[16][200]  = 54528 B
__global__ void __launch_bounds__(256) k_lstm1(const float* __restrict__ edge)
{
    extern __shared__ char smem[];
    uint32_t* sA = (uint32_t*)smem;                 //  8448 B
    float*    sG = (float*)(smem + 8448);           // 33280 B
    float*    sx = (float*)(smem + 41728);          // 12800 B

    const int dir = blockIdx.y;
    const int b0  = blockIdx.x * 16;
    const int tid = threadIdx.x;
    const int wid = tid >> 5, lane = tid & 31;
    const int g   = lane >> 2, tg = lane & 3;
    const int hh  = tid & 127, half = tid >> 7;

    for (int i=tid; i<16*T_SZ; i+=256){
        int b = i / T_SZ, t = i % T_SZ;
        sx[b*T_SZ + t] = edge[(b0+b)*T_SZ + t];
    }
    for (int i=tid; i<16*132; i+=256) sA[i] = 0u;

    float c[8];
    #pragma unroll
    for (int q=0;q<8;q++) c[q] = 0.0f;

    const float4 wi = ((const float4*)g_l1_wih[dir])[hh];
    const float4 bb = ((const float4*)g_l1_b[dir])[hh];
    const u64* __restrict__ WF = (const u64*)g_l1_whhF[dir];
    __syncthreads();

    for (int s=0; s<T_SZ; s++){
        const int t = dir ? (T_SZ-1-s) : s;

        float acc[8][4];
        #pragma unroll
        for (int j=0;j<8;j++)
            #pragma unroll
            for (int q=0;q<4;q++) acc[j][q] = 0.0f;

        #pragma unroll
        for (int kt=0;kt<16;kt++){
            uint32_t a0 = sA[g*132     + kt*8 + tg];
            uint32_t a1 = sA[(g+8)*132 + kt*8 + tg];
            uint32_t a2 = sA[g*132     + kt*8 + tg + 4];
            uint32_t a3 = sA[(g+8)*132 + kt*8 + tg + 4];
            #pragma unroll
            for (int j=0;j<8;j++){
                u64 wv = WF[((wid*16 + kt)*8 + j)*32 + lane];
                uint32_t bw0 = (uint32_t)wv, bw1 = (uint32_t)(wv>>32);
                asm("mma.sync.aligned.m16n8k8.row.col.f32.tf32.tf32.f32 "
                    "{%0,%1,%2,%3}, {%4,%5,%6,%7}, {%8,%9}, {%0,%1,%2,%3};"
                    : "+f"(acc[j][0]), "+f"(acc[j][1]), "+f"(acc[j][2]), "+f"(acc[j][3])
                    : "r"(a0), "r"(a1), "r"(a2), "r"(a3), "r"(bw0), "r"(bw1));
            }
        }
        #pragma unroll
        for (int j=0;j<8;j++){
            int colb = wid*64 + j*8 + 2*tg;
            *(float2*)&sG[g*520 + colb]     = make_float2(acc[j][0], acc[j][1]);
            *(float2*)&sG[(g+8)*520 + colb] = make_float2(acc[j][2], acc[j][3]);
        }
        __syncthreads();

        float* outp = g_h1out + (size_t)t*(B_SZ*256) + (size_t)(b0 + half*8)*256 + dir*128 + hh;
        #pragma unroll
        for (int q=0;q<8;q++){
            int b = half*8 + q;
            float4 gt = *(float4*)&sG[b*520 + 4*hh];
            float xv = sx[b*T_SZ + t];
            float gi = fmaf(wi.x, xv, gt.x + bb.x);
            float gf = fmaf(wi.y, xv, gt.y + bb.y);
            float gg = fmaf(wi.z, xv, gt.z + bb.z);
            float go = fmaf(wi.w, xv, gt.w + bb.w);
            float ig = sigf(gi), fg = sigf(gf), cg = tanhfast(gg), og = sigf(go);
            c[q] = fmaf(fg, c[q], ig*cg);
            float h = og * tanhfast(c[q]);
            sA[b*132 + hh] = f2tf32(h);
            outp[q*256] = h;
            if (s == T_SZ-1) g_hn[dir][(b0+b)*128 + hh] = h;
        }
        __syncthreads();
    }
}

// ---------------- L2 input projection: tf32 tensor-core GEMM (unchanged, proven) ----------------
__global__ void __launch_bounds__(256) k_proj()
{
    const int dir = blockIdx.z;
    const int c0  = blockIdx.y * 128;
    const size_t r0 = (size_t)blockIdx.x * 128;
    const int tid  = threadIdx.x;
    const int wid  = tid >> 5;
    const int lane = tid & 31;
    const int wm = wid >> 2;
    const int wn = wid & 3;
    const int g  = lane >> 2;
    const int tg = lane & 3;

    __shared__ float sA[128][36];
    __shared__ float sB[32][136];

    float acc[4][4][4];
    #pragma unroll
    for (int i=0;i<4;i++)
        #pragma unroll
        for (int j=0;j<4;j++)
            #pragma unroll
            for (int q=0;q<4;q++) acc[i][j][q] = 0.0f;

    const int arow = tid >> 1;
    const int acol = (tid & 1) * 16;
    const int brow = tid >> 3;
    const int bcol = (tid & 7) * 16;
    const float* __restrict__ Asrc = g_h1out + (r0 + arow)*256 + acol;
    const float* __restrict__ Bsrc = g_l2_wihT[dir] + (size_t)brow*512 + c0 + bcol;

    for (int ks=0; ks<256; ks+=32){
        __syncthreads();
        #pragma unroll
        for (int v=0; v<4; v++){
            float4 a = *(const float4*)(Asrc + ks + v*4);
            uint4 ua = make_uint4(f2tf32(a.x), f2tf32(a.y), f2tf32(a.z), f2tf32(a.w));
            *(uint4*)&sA[arow][acol + v*4] = ua;
        }
        #pragma unroll
        for (int v=0; v<4; v++){
            float4 b = *(const float4*)(Bsrc + (size_t)ks*512 + v*4);
            uint4 ub = make_uint4(f2tf32(b.x), f2tf32(b.y), f2tf32(b.z), f2tf32(b.w));
            *(uint4*)&sB[brow][bcol + v*4] = ub;
        }
        __syncthreads();

        #pragma unroll
        for (int kt=0; kt<4; kt++){
            uint32_t bf[4][2];
            #pragma unroll
            for (int j=0;j<4;j++){
                int col = wn*32 + j*8 + g;
                bf[j][0] = *(const uint32_t*)&sB[kt*8 + tg    ][col];
                bf[j][1] = *(const uint32_t*)&sB[kt*8 + tg + 4][col];
            }
            #pragma unroll
            for (int i=0;i<4;i++){
                int r = wm*64 + i*16;
                uint32_t a0 = *(const uint32_t*)&sA[r + g    ][kt*8 + tg    ];
                uint32_t a1 = *(const uint32_t*)&sA[r + g + 8][kt*8 + tg    ];
                uint32_t a2 = *(const uint32_t*)&sA[r + g    ][kt*8 + tg + 4];
                uint32_t a3 = *(const uint32_t*)&sA[r + g + 8][kt*8 + tg + 4];
                #pragma unroll
                for (int j=0;j<4;j++){
                    asm("mma.sync.aligned.m16n8k8.row.col.f32.tf32.tf32.f32 "
                        "{%0,%1,%2,%3}, {%4,%5,%6,%7}, {%8,%9}, {%0,%1,%2,%3};"
                        : "+f"(acc[i][j][0]), "+f"(acc[i][j][1]),
                          "+f"(acc[i][j][2]), "+f"(acc[i][j][3])
                        : "r"(a0), "r"(a1), "r"(a2), "r"(a3),
                          "r"(bf[j][0]), "r"(bf[j][1]));
                }
            }
        }
    }

    float* __restrict__ C = g_preact[dir];
    #pragma unroll
    for (int j=0;j<4;j++){
        int col = c0 + wn*32 + j*8 + 2*tg;
        float2 bias = *(const float2*)&g_l2_b[dir][col];
        #pragma unroll
        for (int i=0;i<4;i++){
            size_t rA = r0 + wm*64 + i*16 + g;
            float2 v0 = make_float2(acc[i][j][0]+bias.x, acc[i][j][1]+bias.y);
            float2 v1 = make_float2(acc[i][j][2]+bias.x, acc[i][j][3]+bias.y);
            *(float2*)&C[rA*512 + col]     = v0;
            *(float2*)&C[(rA+8)*512 + col] = v1;
        }
    }
}

// ---------------- BiLSTM layer 2: tensor-core recurrent scan, 16 rows/CTA, preact prefetch ----------------
// smem: sA u32[16][132] | sG float[16][520]  = 41728 B
__global__ void __launch_bounds__(256) k_lstm2()
{
    extern __shared__ char smem[];
    uint32_t* sA = (uint32_t*)smem;
    float*    sG = (float*)(smem + 8448);

    const int dir = blockIdx.y;
    const int b0  = blockIdx.x * 16;
    const int tid = threadIdx.x;
    const int wid = tid >> 5, lane = tid & 31;
    const int g   = lane >> 2, tg = lane & 3;
    const int hh  = tid & 127, half = tid >> 7;

    for (int i=tid; i<16*132; i+=256) sA[i] = 0u;
    float c[8];
    #pragma unroll
    for (int q=0;q<8;q++) c[q] = 0.0f;

    const u64* __restrict__ WF = (const u64*)g_l2_whhF[dir];
    const float* __restrict__ pre = g_preact[dir];
    __syncthreads();

    for (int s=0; s<T_SZ; s++){
        const int t = dir ? (T_SZ-1-s) : s;

        // prefetch preact (independent of h) — overlaps the mma phase
        float4 p[8];
        #pragma unroll
        for (int q=0;q<8;q++)
            p[q] = *(const float4*)&pre[((size_t)t*B_SZ + b0 + half*8 + q)*512 + 4*hh];

        float acc[8][4];
        #pragma unroll
        for (int j=0;j<8;j++)
            #pragma unroll
            for (int q=0;q<4;q++) acc[j][q] = 0.0f;

        #pragma unroll
        for (int kt=0;kt<16;kt++){
            uint32_t a0 = sA[g*132     + kt*8 + tg];
            uint32_t a1 = sA[(g+8)*132 + kt*8 + tg];
            uint32_t a2 = sA[g*132     + kt*8 + tg + 4];
            uint32_t a3 = sA[(g+8)*132 + kt*8 + tg + 4];
            #pragma unroll
            for (int j=0;j<8;j++){
                u64 wv = WF[((wid*16 + kt)*8 + j)*32 + lane];
                uint32_t bw0 = (uint32_t)wv, bw1 = (uint32_t)(wv>>32);
                asm("mma.sync.aligned.m16n8k8.row.col.f32.tf32.tf32.f32 "
                    "{%0,%1,%2,%3}, {%4,%5,%6,%7}, {%8,%9}, {%0,%1,%2,%3};"
                    : "+f"(acc[j][0]), "+f"(acc[j][1]), "+f"(acc[j][2]), "+f"(acc[j][3])
                    : "r"(a0), "r"(a1), "r"(a2), "r"(a3), "r"(bw0), "r"(bw1));
            }
        }
        #pragma unroll
        for (int j=0;j<8;j++){
            int colb = wid*64 + j*8 + 2*tg;
            *(float2*)&sG[g*520 + colb]     = make_float2(acc[j][0], acc[j][1]);
            *(float2*)&sG[(g+8)*520 + colb] = make_float2(acc[j][2], acc[j][3]);
        }
        __syncthreads();

        #pragma unroll
        for (int q=0;q<8;q++){
            int b = half*8 + q;
            float4 gt = *(float4*)&sG[b*520 + 4*hh];
            float ig = sigf(gt.x + p[q].x);
            float fg = sigf(gt.y + p[q].y);
            float cg = tanhfast(gt.z + p[q].z);
            float og = sigf(gt.w + p[q].w);
            c[q] = fmaf(fg, c[q], ig*cg);
            float h = og * tanhfast(c[q]);
            sA[b*132 + hh] = f2tf32(h);
            if (s == T_SZ-1) g_hn[2+dir][(b0+b)*128 + hh] = h;
        }
        __syncthreads();
    }
}

// ---------------- FC head ----------------
__global__ void __launch_bounds__(256) k_fc(const int* __restrict__ node_data,
                                            const float* __restrict__ emb,
                                            const float* __restrict__ fc1_b,
                                            const float* __restrict__ fc2_b)
{
    const int r = blockIdx.x;
    const int c = threadIdx.x;
    __shared__ float sh_in[256];
    __shared__ float sh_mid[256];

    int d = r >> 10;
    int b = ((r & 1023) << 1) + (c >> 7);
    int k = c & 127;
    sh_in[c] = g_hn[d][b*128 + k] + g_hn[2+d][b*128 + k];
    __syncthreads();

    float acc = fc1_b[c];
    #pragma unroll 4
    for (int i=0;i<256;i++) acc = fmaf(sh_in[i], g_fc1_wT[i*256 + c], acc);
    sh_mid[c] = sigf(acc);
    __syncthreads();

    if (c < 64){
        float a2 = fc2_b[c];
        #pragma unroll 4
        for (int i=0;i<256;i++) a2 = fmaf(sh_mid[i], g_fc2_wT[i*64 + c], a2);
        g_hidden[r*128 + c] = sigf(a2);
    } else if (c < 128){
        int e = c - 64;
        int n0 = node_data[r*2], n1 = node_data[r*2+1];
        g_hidden[r*128 + 64 + e] = 0.5f*(emb[n0*64 + e] + emb[n1*64 + e]);
    }
}

// ---------------- decoder: tensor-core GRU scans (unchanged, proven) ----------------
__global__ void __launch_bounds__(256) k_dec(const float* __restrict__ edge,
                                             const float* __restrict__ g2_bih,
                                             const float* __restrict__ g2_bhh,
                                             const float* __restrict__ dec_w,
                                             const float* __restrict__ dec_b,
                                             float* __restrict__ out)
{
    extern __shared__ char smem[];
    uint32_t* sA  = (uint32_t*)smem;               // [16][196]  12544 B
    float*    sG  = (float*)(smem + 12544);        // [16][520]  33280 B
    float*    sGB = (float*)(smem + 45824);        // [16][200]  12800 B
    float*    h2s = (float*)(smem + 58624);        // [16][52]    3328 B
    float*    res = (float*)(smem + 61952);        // [16]
    float*    dw  = (float*)(smem + 62016);        // [52]

    const int b0  = blockIdx.x * 16;
    const int tid = threadIdx.x;
    const int wid = tid >> 5, lane = tid & 31;
    const int g   = lane >> 2, tg = lane & 3;
    const int hh  = tid & 127, half = tid >> 7;
    const int n2  = tid & 63;
    const int half2 = (tid >> 6) & 1;
    const bool c_act = (tid < 128) && (n2 < 50);

    for (int i=tid; i<16*196; i+=256) sA[i] = 0u;
    if (tid < 52) dw[tid] = (tid < 50) ? dec_w[tid] : 0.0f;
    if (tid < 16) res[tid] = edge[(b0+tid)*T_SZ + (T_SZ-1)];
    __syncthreads();

    float h1[8];
    #pragma unroll
    for (int q=0;q<8;q++){
        int b = half*8 + q;
        h1[q] = g_hidden[(b0+b)*128 + hh];
        sA[b*196 + hh] = f2tf32(h1[q]);
    }
    float h2[8];
    #pragma unroll
    for (int q=0;q<8;q++) h2[q] = 0.0f;
    if (c_act){
        #pragma unroll
        for (int q=0;q<8;q++) h2s[(half2*8+q)*52 + n2] = 0.0f;
    }

    const float4 wi = ((const float4*)g_g1_wih)[hh];
    const float4 bi = ((const float4*)g_g1_bih)[hh];
    const float4 bh = ((const float4*)g_g1_bhh)[hh];
    float bBr=0.f, bBz=0.f, bBi=0.f, bBh=0.f;
    if (c_act){
        bBr = g2_bih[n2]     + g2_bhh[n2];
        bBz = g2_bih[50+n2]  + g2_bhh[50+n2];
        bBi = g2_bih[100+n2];
        bBh = g2_bhh[100+n2];
    }
    const float decb = dec_b[0];
    const u64* __restrict__ WF1 = (const u64*)g_g1F;
    const u64* __restrict__ WF2 = (const u64*)g_g2F;
    __syncthreads();

    for (int t=0; t<T_SZ; t++){
        // ---- Phase A: GRU1 hidden matvec (all 8 warps) ----
        float acc[8][4];
        #pragma unroll
        for (int j=0;j<8;j++)
            #pragma unroll
            for (int q=0;q<4;q++) acc[j][q] = 0.0f;
        #pragma unroll
        for (int kt=0;kt<16;kt++){
            uint32_t a0 = sA[g*196     + kt*8 + tg];
            uint32_t a1 = sA[(g+8)*196 + kt*8 + tg];
            uint32_t a2 = sA[g*196     + kt*8 + tg + 4];
            uint32_t a3 = sA[(g+8)*196 + kt*8 + tg + 4];
            #pragma unroll
            for (int j=0;j<8;j++){
                u64 wv = WF1[((wid*16 + kt)*8 + j)*32 + lane];
                uint32_t bw0 = (uint32_t)wv, bw1 = (uint32_t)(wv>>32);
                asm("mma.sync.aligned.m16n8k8.row.col.f32.tf32.tf32.f32 "
                    "{%0,%1,%2,%3}, {%4,%5,%6,%7}, {%8,%9}, {%0,%1,%2,%3};"
                    : "+f"(acc[j][0]), "+f"(acc[j][1]), "+f"(acc[j][2]), "+f"(acc[j][3])
                    : "r"(a0), "r"(a1), "r"(a2), "r"(a3), "r"(bw0), "r"(bw1));
            }
        }
        #pragma unroll
        for (int j=0;j<8;j++){
            int colb = wid*64 + j*8 + 2*tg;
            *(float2*)&sG[g*520 + colb]     = make_float2(acc[j][0], acc[j][1]);
            *(float2*)&sG[(g+8)*520 + colb] = make_float2(acc[j][2], acc[j][3]);
        }
        __syncthreads();

        // ---- EpiA: GRU1 combine ----
        #pragma unroll
        for (int q=0;q<8;q++){
            int b = half*8 + q;
            float4 gt = *(float4*)&sG[b*520 + 4*hh];
            float rv = res[b];
            float rg = sigf( fmaf(wi.x, rv, bi.x) + gt.x + bh.x );
            float zg = sigf( fmaf(wi.y, rv, bi.y) + gt.y + bh.y );
            float ng = tanhfast( fmaf(wi.z, rv, bi.z) + rg*(gt.z + bh.z) );
            h1[q] = fmaf(zg, h1[q] - ng, ng);
            sA[b*196 + hh] = f2tf32(h1[q]);
        }
        __syncthreads();

        // ---- Phase B: GRU2 [r|z|inn|hn] over [h1n|h2] (warps 0-3) ----
        if (wid < 4){
            float ac2[8][4];
            #pragma unroll
            for (int j=0;j<8;j++)
                #pragma unroll
                for (int q=0;q<4;q++) ac2[j][q] = 0.0f;
            #pragma unroll
            for (int kt=0;kt<24;kt++){
                uint32_t a0 = sA[g*196     + kt*8 + tg];
                uint32_t a1 = sA[(g+8)*196 + kt*8 + tg];
                uint32_t a2 = sA[g*196     + kt*8 + tg + 4];
                uint32_t a3 = sA[(g+8)*196 + kt*8 + tg + 4];
                #pragma unroll
                for (int j=0;j<8;j++){
                    u64 wv = WF2[((wid*24 + kt)*8 + j)*32 + lane];
                    uint32_t bw0 = (uint32_t)wv, bw1 = (uint32_t)(wv>>32);
                    asm("mma.sync.aligned.m16n8k8.row.col.f32.tf32.tf32.f32 "
                        "{%0,%1,%2,%3}, {%4,%5,%6,%7}, {%8,%9}, {%0,%1,%2,%3};"
                        : "+f"(ac2[j][0]), "+f"(ac2[j][1]), "+f"(ac2[j][2]), "+f"(ac2[j][3])
                        : "r"(a0), "r"(a1), "r"(a2), "r"(a3), "r"(bw0), "r"(bw1));
                }
            }
            #pragma unroll
            for (int j=0;j<8;j++){
                int colb = wid*64 + j*8 + 2*tg;
                *(float2*)&sGB[g*200 + colb]     = make_float2(ac2[j][0], ac2[j][1]);
                *(float2*)&sGB[(g+8)*200 + colb] = make_float2(ac2[j][2], ac2[j][3]);
            }
        }
        __syncthreads();

        // ---- EpiC: GRU2 combine ----
        if (c_act){
            #pragma unroll
            for (int q=0;q<8;q++){
                int b = half2*8 + q;
                float r2 = sigf(sGB[b*200 + n2]      + bBr);
                float z2 = sigf(sGB[b*200 + 50 + n2] + bBz);
                float nn = tanhfast( (sGB[b*200 + 100 + n2] + bBi) + r2*(sGB[b*200 + 150 + n2] + bBh) );
                h2[q] = fmaf(z2, h2[q] - nn, nn);
                sA[b*196 + 128 + n2] = f2tf32(h2[q]);
                h2s[b*52 + n2] = h2[q];
            }
        }
        __syncthreads();

        // ---- Phase D: decoder dot + sigmoid ----
        if (tid < 16){
            float s = decb;
            #pragma unroll 2
            for (int k=0;k<50;k++) s = fmaf(h2s[tid*52 + k], dw[k], s);
            float r = sigf(s);
            res[tid] = r;
            out[(b0+tid)*T_SZ + t] = r;
        }
        __syncthreads();
    }
}

extern "C" void kernel_launch(void* const* d_in, const int* in_sizes, int n_in,
                              void* d_out, int out_size)
{
    const int*   node_data = (const int*)  d_in[0];
    const float* edge_data = (const float*)d_in[1];
    const float* emb       = (const float*)d_in[2];
    const float* l1_wih_f  = (const float*)d_in[3];
    const float* l1_whh_f  = (const float*)d_in[4];
    const float* l1_b_f    = (const float*)d_in[5];
    const float* l1_wih_b  = (const float*)d_in[6];
    const float* l1_whh_b  = (const float*)d_in[7];
    const float* l1_b_b    = (const float*)d_in[8];
    const float* l2_wih_f  = (const float*)d_in[9];
    const float* l2_whh_f  = (const float*)d_in[10];
    const float* l2_b_f    = (const float*)d_in[11];
    const float* l2_wih_b  = (const float*)d_in[12];
    const float* l2_whh_b  = (const float*)d_in[13];
    const float* l2_b_b    = (const float*)d_in[14];
    const float* fc1_w     = (const float*)d_in[15];
    const float* fc1_b     = (const float*)d_in[16];
    const float* fc2_w     = (const float*)d_in[17];
    const float* fc2_b     = (const float*)d_in[18];
    const float* g1_wih    = (const float*)d_in[19];
    const float* g1_whh    = (const float*)d_in[20];
    const float* g1_bih    = (const float*)d_in[21];
    const float* g1_bhh    = (const float*)d_in[22];
    const float* g2_wih    = (const float*)d_in[23];
    const float* g2_whh    = (const float*)d_in[24];
    const float* g2_bih    = (const float*)d_in[25];
    const float* g2_bhh    = (const float*)d_in[26];
    const float* dec_w     = (const float*)d_in[27];
    const float* dec_b     = (const float*)d_in[28];
    float* out = (float*)d_out;

    cudaFuncSetAttribute(k_lstm1, cudaFuncAttributeMaxDynamicSharedMemorySize, 54528);
    cudaFuncSetAttribute(k_lstm2, cudaFuncAttributeMaxDynamicSharedMemorySize, 41728);
    cudaFuncSetAttribute(k_dec,   cudaFuncAttributeMaxDynamicSharedMemorySize, 62464);

    k_prep<<<256, 256>>>(l1_wih_f, l1_whh_f, l1_b_f, l1_wih_b, l1_whh_b, l1_b_b,
                         l2_wih_f, l2_whh_f, l2_b_f, l2_wih_b, l2_whh_b, l2_b_b,
                         fc1_w, fc2_w, g1_wih, g1_whh, g1_bih, g1_bhh,
                         g2_wih, g2_whh);
    k_lstm1<<<dim3(B_SZ/16, 2), 256, 54528>>>(edge_data);
    k_proj<<<dim3((T_SZ*B_SZ)/128, 4, 2), 256>>>();
    k_lstm2<<<dim3(B_SZ/16, 2), 256, 41728>>>();
    k_fc<<<B_SZ, 256>>>(node_data, emb, fc1_b, fc2_b);
    k_dec<<<B_SZ/16, 256, 62464>>>(edge_data, g2_bih, g2_bhh, dec_w, dec_b, out);
}

// round 17
// speedup vs baseline: 3.3609x; 1.0424x over previous
#include <cuda_runtime.h>
#include <cuda_bf16.h>
#include <math.h>
#include <stdint.h>

#define B_SZ 2048
#define T_SZ 200

typedef unsigned long long u64;

// ---- fast activations ----
__device__ __forceinline__ float fex2(float x){ float r; asm("ex2.approx.f32 %0, %1;" : "=f"(r) : "f"(x)); return r; }
__device__ __forceinline__ float frcp(float x){ float r; asm("rcp.approx.f32 %0, %1;" : "=f"(r) : "f"(x)); return r; }
#define LOG2E 1.4426950408889634f
__device__ __forceinline__ float sigf(float x){
    return frcp(1.0f + fex2(-LOG2E*x));
}
__device__ __forceinline__ float tanhfast(float x){
    float t = fminf(2.0f*LOG2E*x, 126.0f);
    float e = fex2(t);
    return (e - 1.0f) * frcp(e + 1.0f);
}
__device__ __forceinline__ uint32_t f2tf32(float x){
    uint32_t r; asm("cvt.rna.tf32.f32 %0, %1;" : "=r"(r) : "f"(x)); return r;
}
__device__ __forceinline__ uint32_t packbf2(float lo, float hi){
    __nv_bfloat162 v = __floats2bfloat162_rn(lo, hi);
    return *(uint32_t*)&v;
}

// ---------------- device scratch ----------------
__device__ __align__(16) uint32_t g_l1_whhB[2][32768]; // frag-linear bf16 recurrent weights (k16)
__device__ __align__(16) uint32_t g_l2_whhB[2][32768];
__device__ __align__(16) float g_l1_wih [2][512];
__device__ __align__(16) float g_l1_b   [2][512];
__device__ __align__(16) float g_l2_wihT[2][256*512];
__device__ __align__(16) float g_l2_b   [2][512];
__device__ __align__(16) float g_fc1_wT[256*256];
__device__ __align__(16) float g_fc2_wT[256*64];
__device__ __align__(16) float g_g1F[65536];          // GRU1 Whh frag-linear tf32 (quad r,z,n,0)
__device__ __align__(16) float g_g2F[49152];          // GRU2 combined [r|z|inn|hn] frag-linear tf32
__device__ __align__(16) float g_g1_wih[512];
__device__ __align__(16) float g_g1_bih[512];
__device__ __align__(16) float g_g1_bhh[512];
__device__ __align__(16) float g_h1out[(size_t)T_SZ*B_SZ*256];      // [t][b][256]
__device__ __align__(16) float g_preact[2][(size_t)T_SZ*B_SZ*512];  // [dir][t*B+b][512]
__device__ __align__(16) float g_hn[4][B_SZ*128];
__device__ __align__(16) float g_hidden[B_SZ*128];

// ---------------- weight permutation ----------------
__global__ void k_prep(
    const float* __restrict__ l1_wih_f, const float* __restrict__ l1_whh_f, const float* __restrict__ l1_b_f,
    const float* __restrict__ l1_wih_b, const float* __restrict__ l1_whh_b, const float* __restrict__ l1_b_b,
    const float* __restrict__ l2_wih_f, const float* __restrict__ l2_whh_f, const float* __restrict__ l2_b_f,
    const float* __restrict__ l2_wih_b, const float* __restrict__ l2_whh_b, const float* __restrict__ l2_b_b,
    const float* __restrict__ fc1_w, const float* __restrict__ fc2_w,
    const float* __restrict__ g1_wih, const float* __restrict__ g1_whh,
    const float* __restrict__ g1_bih, const float* __restrict__ g1_bhh,
    const float* __restrict__ g2_wih, const float* __restrict__ g2_whh)
{
    const int idx = blockIdx.x*blockDim.x + threadIdx.x;
    const int stride = gridDim.x*blockDim.x;

    // bf16 k16 frag-linear: u32 x = ((((w*8+kt)*8+j)*32)+lane)*2 + r
    // word holds bf16 pair W[col][k0], W[col][k0+1], k0 = kt*16 + 2tg + 8r
    for (int i=idx; i<2*32768; i+=stride){
        int dir = i>>15, x = i&32767;
        int r=(x&1), lane=(x>>1)&31, j=(x>>6)&7, kt=(x>>9)&7, w=(x>>12)&7;
        int g=lane>>2, tg=lane&3;
        int k0 = kt*16 + 2*tg + 8*r;
        int col = w*64 + j*8 + g;
        int srow = (col&3)*128 + (col>>2);
        const float* s1 = dir ? l1_whh_b : l1_whh_f;
        const float* s2 = dir ? l2_whh_b : l2_whh_f;
        g_l1_whhB[dir][x] = packbf2(s1[srow*128+k0], s1[srow*128+k0+1]);
        g_l2_whhB[dir][x] = packbf2(s2[srow*128+k0], s2[srow*128+k0+1]);
    }
    for (int i=idx; i<65536; i+=stride){              // GRU1 Whh frag-linear tf32
        int x = i;
        int r = x&1, lane = (x>>1)&31, j = (x>>6)&7, kt = (x>>9)&15, w = (x>>13)&7;
        int g = lane>>2, tg = lane&3;
        int k = kt*8 + tg + 4*r;
        int col = w*64 + j*8 + g;
        int h = col>>2, q = col&3;
        float v = (q<3) ? g1_whh[(q*128+h)*128 + k] : 0.0f;
        g_g1F[x] = __uint_as_float(f2tf32(v));
    }
    for (int i=idx; i<49152; i+=stride){              // GRU2 combined frag-linear tf32
        int x = i;
        int r = x&1, lane = (x>>1)&31, j = (x>>6)&7;
        int rem = x>>9;
        int kt = rem % 24, w = rem / 24;
        int g = lane>>2, tg = lane&3;
        int k = kt*8 + tg + 4*r;
        int col = w*64 + j*8 + g;
        float v = 0.0f;
        if (col < 100){
            if (k < 128)            v = g2_wih[col*128 + k];
            else if (k < 178)       v = g2_whh[col*50 + (k-128)];
        } else if (col < 150){
            if (k < 128)            v = g2_wih[col*128 + k];
        } else if (col < 200){
            if (k >= 128 && k < 178) v = g2_whh[(col-50)*50 + (k-128)];
        }
        g_g2F[x] = __uint_as_float(f2tf32(v));
    }
    for (int i=idx; i<2*256*512; i+=stride){          // L2 wih^T (for k_proj)
        int dir=i>>17, r=i&131071, k=r>>9, col=r&511, h=col>>2, q=col&3;
        const float* s = dir ? l2_wih_b : l2_wih_f;
        g_l2_wihT[dir][r] = s[(q*128+h)*256 + k];
    }
    for (int i=idx; i<2*512; i+=stride){
        int dir=i>>9, col=i&511, h=col>>2, q=col&3, g=q*128+h;
        g_l1_wih[dir][col] = (dir ? l1_wih_b : l1_wih_f)[g];
        g_l1_b  [dir][col] = (dir ? l1_b_b   : l1_b_f  )[g];
        g_l2_b  [dir][col] = (dir ? l2_b_b   : l2_b_f  )[g];
    }
    for (int i=idx; i<256*256; i+=stride){
        int c=i>>8, j=i&255;
        g_fc1_wT[i] = fc1_w[j*256+c];
    }
    for (int i=idx; i<256*64; i+=stride){
        int c=i>>6, j=i&63;
        g_fc2_wT[i] = fc2_w[j*256+c];
    }
    for (int i=idx; i<512; i+=stride){
        int h=i>>2, q=i&3;
        g_g1_wih[i] = (q<3) ? g1_wih[q*128+h] : 0.0f;
        g_g1_bih[i] = (q<3) ? g1_bih[q*128+h] : 0.0f;
        g_g1_bhh[i] = (q<3) ? g1_bhh[q*128+h] : 0.0f;
    }
}

// h -> sA(bf16) write index for hidden k=hh: word kt*8+u, byte rem&1
__device__ __forceinline__ int h_word(int hh){
    int kt = hh>>4, rem = hh&15;
    int u = (rem<8) ? (rem>>1) : (4 + ((rem-8)>>1));
    return kt*8 + u;
}

// ---------------- BiLSTM layer 1: bf16-k16 tensor scan, 16 rows/CTA, 2 CTAs/SM ----------------
// smem: sA u32[16][132] (bf16 pairs, k-words 0..63 used) | sG float[16][520] | sx float[16][200]
__global__ void __launch_bounds__(256) k_lstm1(const float* __restrict__ edge)
{
    extern __shared__ char smem[];
    uint32_t* sA = (uint32_t*)smem;                 //  8448 B
    float*    sG = (float*)(smem + 8448);           // 33280 B
    float*    sx = (float*)(smem + 41728);          // 12800 B

    const int dir = blockIdx.y;
    const int b0  = blockIdx.x * 16;
    const int tid = threadIdx.x;
    const int wid = tid >> 5, lane = tid & 31;
    const int g   = lane >> 2, tg = lane & 3;
    const int hh  = tid & 127, half = tid >> 7;
    const int hw  = h_word(hh), hb_byte = hh & 1;

    for (int i=tid; i<16*T_SZ; i+=256){
        int b = i / T_SZ, t = i % T_SZ;
        sx[b*T_SZ + t] = edge[(b0+b)*T_SZ + t];
    }
    for (int i=tid; i<16*132; i+=256) sA[i] = 0u;

    float c[8];
    #pragma unroll
    for (int q=0;q<8;q++) c[q] = 0.0f;

    const float4 wi = ((const float4*)g_l1_wih[dir])[hh];
    const float4 bb = ((const float4*)g_l1_b[dir])[hh];
    const u64* __restrict__ WF = (const u64*)g_l1_whhB[dir];
    __syncthreads();

    for (int s=0; s<T_SZ; s++){
        const int t = dir ? (T_SZ-1-s) : s;

        float acc[8][4];
        #pragma unroll
        for (int j=0;j<8;j++)
            #pragma unroll
            for (int q=0;q<4;q++) acc[j][q] = 0.0f;

        #pragma unroll
        for (int kt=0;kt<8;kt++){
            uint32_t a0 = sA[g*132     + kt*8 + tg];
            uint32_t a1 = sA[(g+8)*132 + kt*8 + tg];
            uint32_t a2 = sA[g*132     + kt*8 + tg + 4];
            uint32_t a3 = sA[(g+8)*132 + kt*8 + tg + 4];
            #pragma unroll
            for (int j=0;j<8;j++){
                u64 wv = WF[((wid*8 + kt)*8 + j)*32 + lane];
                uint32_t bw0 = (uint32_t)wv, bw1 = (uint32_t)(wv>>32);
                asm("mma.sync.aligned.m16n8k16.row.col.f32.bf16.bf16.f32 "
                    "{%0,%1,%2,%3}, {%4,%5,%6,%7}, {%8,%9}, {%0,%1,%2,%3};"
                    : "+f"(acc[j][0]), "+f"(acc[j][1]), "+f"(acc[j][2]), "+f"(acc[j][3])
                    : "r"(a0), "r"(a1), "r"(a2), "r"(a3), "r"(bw0), "r"(bw1));
            }
        }
        #pragma unroll
        for (int j=0;j<8;j++){
            int colb = wid*64 + j*8 + 2*tg;
            *(float2*)&sG[g*520 + colb]     = make_float2(acc[j][0], acc[j][1]);
            *(float2*)&sG[(g+8)*520 + colb] = make_float2(acc[j][2], acc[j][3]);
        }
        __syncthreads();

        float* outp = g_h1out + (size_t)t*(B_SZ*256) + (size_t)(b0 + half*8)*256 + dir*128 + hh;
        #pragma unroll
        for (int q=0;q<8;q++){
            int b = half*8 + q;
            float4 gt = *(float4*)&sG[b*520 + 4*hh];
            float xv = sx[b*T_SZ + t];
            float gi = fmaf(wi.x, xv, gt.x + bb.x);
            float gf = fmaf(wi.y, xv, gt.y + bb.y);
            float gg = fmaf(wi.z, xv, gt.z + bb.z);
            float go = fmaf(wi.w, xv, gt.w + bb.w);
            float ig = sigf(gi), fg = sigf(gf), cg = tanhfast(gg), og = sigf(go);
            c[q] = fmaf(fg, c[q], ig*cg);
            float h = og * tanhfast(c[q]);
            ((__nv_bfloat16*)sA)[(b*132 + hw)*2 + hb_byte] = __float2bfloat16(h);
            outp[q*256] = h;
            if (s == T_SZ-1) g_hn[dir][(b0+b)*128 + hh] = h;
        }
        __syncthreads();
    }
}

// ---------------- L2 input projection: tf32 GEMM, cb-adjacent grid for A reuse ----------------
__global__ void __launch_bounds__(256) k_proj()
{
    const int dir = blockIdx.z;
    const int c0  = (blockIdx.x & 3) * 128;
    const size_t r0 = (size_t)(blockIdx.x >> 2) * 128;
    const int tid  = threadIdx.x;
    const int wid  = tid >> 5;
    const int lane = tid & 31;
    const int wm = wid >> 2;
    const int wn = wid & 3;
    const int g  = lane >> 2;
    const int tg = lane & 3;

    __shared__ float sA[128][36];
    __shared__ float sB[32][136];

    float acc[4][4][4];
    #pragma unroll
    for (int i=0;i<4;i++)
        #pragma unroll
        for (int j=0;j<4;j++)
            #pragma unroll
            for (int q=0;q<4;q++) acc[i][j][q] = 0.0f;

    const int arow = tid >> 1;
    const int acol = (tid & 1) * 16;
    const int brow = tid >> 3;
    const int bcol = (tid & 7) * 16;
    const float* __restrict__ Asrc = g_h1out + (r0 + arow)*256 + acol;
    const float* __restrict__ Bsrc = g_l2_wihT[dir] + (size_t)brow*512 + c0 + bcol;

    for (int ks=0; ks<256; ks+=32){
        __syncthreads();
        #pragma unroll
        for (int v=0; v<4; v++){
            float4 a = *(const float4*)(Asrc + ks + v*4);
            uint4 ua = make_uint4(f2tf32(a.x), f2tf32(a.y), f2tf32(a.z), f2tf32(a.w));
            *(uint4*)&sA[arow][acol + v*4] = ua;
        }
        #pragma unroll
        for (int v=0; v<4; v++){
            float4 b = *(const float4*)(Bsrc + (size_t)ks*512 + v*4);
            uint4 ub = make_uint4(f2tf32(b.x), f2tf32(b.y), f2tf32(b.z), f2tf32(b.w));
            *(uint4*)&sB[brow][bcol + v*4] = ub;
        }
        __syncthreads();

        #pragma unroll
        for (int kt=0; kt<4; kt++){
            uint32_t bf[4][2];
            #pragma unroll
            for (int j=0;j<4;j++){
                int col = wn*32 + j*8 + g;
                bf[j][0] = *(const uint32_t*)&sB[kt*8 + tg    ][col];
                bf[j][1] = *(const uint32_t*)&sB[kt*8 + tg + 4][col];
            }
            #pragma unroll
            for (int i=0;i<4;i++){
                int r = wm*64 + i*16;
                uint32_t a0 = *(const uint32_t*)&sA[r + g    ][kt*8 + tg    ];
                uint32_t a1 = *(const uint32_t*)&sA[r + g + 8][kt*8 + tg    ];
                uint32_t a2 = *(const uint32_t*)&sA[r + g    ][kt*8 + tg + 4];
                uint32_t a3 = *(const uint32_t*)&sA[r + g + 8][kt*8 + tg + 4];
                #pragma unroll
                for (int j=0;j<4;j++){
                    asm("mma.sync.aligned.m16n8k8.row.col.f32.tf32.tf32.f32 "
                        "{%0,%1,%2,%3}, {%4,%5,%6,%7}, {%8,%9}, {%0,%1,%2,%3};"
                        : "+f"(acc[i][j][0]), "+f"(acc[i][j][1]),
                          "+f"(acc[i][j][2]), "+f"(acc[i][j][3])
                        : "r"(a0), "r"(a1), "r"(a2), "r"(a3),
                          "r"(bf[j][0]), "r"(bf[j][1]));
                }
            }
        }
    }

    float* __restrict__ C = g_preact[dir];
    #pragma unroll
    for (int j=0;j<4;j++){
        int col = c0 + wn*32 + j*8 + 2*tg;
        float2 bias = *(const float2*)&g_l2_b[dir][col];
        #pragma unroll
        for (int i=0;i<4;i++){
            size_t rA = r0 + wm*64 + i*16 + g;
            float2 v0 = make_float2(acc[i][j][0]+bias.x, acc[i][j][1]+bias.y);
            float2 v1 = make_float2(acc[i][j][2]+bias.x, acc[i][j][3]+bias.y);
            *(float2*)&C[rA*512 + col]     = v0;
            *(float2*)&C[(rA+8)*512 + col] = v1;
        }
    }
}

// ---------------- BiLSTM layer 2: bf16-k16 tensor scan, preact prefetch ----------------
__global__ void __launch_bounds__(256) k_lstm2()
{
    extern __shared__ char smem[];
    uint32_t* sA = (uint32_t*)smem;
    float*    sG = (float*)(smem + 8448);

    const int dir = blockIdx.y;
    const int b0  = blockIdx.x * 16;
    const int tid = threadIdx.x;
    const int wid = tid >> 5, lane = tid & 31;
    const int g   = lane >> 2, tg = lane & 3;
    const int hh  = tid & 127, half = tid >> 7;
    const int hw  = h_word(hh), hb_byte = hh & 1;

    for (int i=tid; i<16*132; i+=256) sA[i] = 0u;
    float c[8];
    #pragma unroll
    for (int q=0;q<8;q++) c[q] = 0.0f;

    const u64* __restrict__ WF = (const u64*)g_l2_whhB[dir];
    const float* __restrict__ pre = g_preact[dir];
    __syncthreads();

    for (int s=0; s<T_SZ; s++){
        const int t = dir ? (T_SZ-1-s) : s;

        float4 p[8];
        #pragma unroll
        for (int q=0;q<8;q++)
            p[q] = *(const float4*)&pre[((size_t)t*B_SZ + b0 + half*8 + q)*512 + 4*hh];

        float acc[8][4];
        #pragma unroll
        for (int j=0;j<8;j++)
            #pragma unroll
            for (int q=0;q<4;q++) acc[j][q] = 0.0f;

        #pragma unroll
        for (int kt=0;kt<8;kt++){
            uint32_t a0 = sA[g*132     + kt*8 + tg];
            uint32_t a1 = sA[(g+8)*132 + kt*8 + tg];
            uint32_t a2 = sA[g*132     + kt*8 + tg + 4];
            uint32_t a3 = sA[(g+8)*132 + kt*8 + tg + 4];
            #pragma unroll
            for (int j=0;j<8;j++){
                u64 wv = WF[((wid*8 + kt)*8 + j)*32 + lane];
                uint32_t bw0 = (uint32_t)wv, bw1 = (uint32_t)(wv>>32);
                asm("mma.sync.aligned.m16n8k16.row.col.f32.bf16.bf16.f32 "
                    "{%0,%1,%2,%3}, {%4,%5,%6,%7}, {%8,%9}, {%0,%1,%2,%3};"
                    : "+f"(acc[j][0]), "+f"(acc[j][1]), "+f"(acc[j][2]), "+f"(acc[j][3])
                    : "r"(a0), "r"(a1), "r"(a2), "r"(a3), "r"(bw0), "r"(bw1));
            }
        }
        #pragma unroll
        for (int j=0;j<8;j++){
            int colb = wid*64 + j*8 + 2*tg;
            *(float2*)&sG[g*520 + colb]     = make_float2(acc[j][0], acc[j][1]);
            *(float2*)&sG[(g+8)*520 + colb] = make_float2(acc[j][2], acc[j][3]);
        }
        __syncthreads();

        #pragma unroll
        for (int q=0;q<8;q++){
            int b = half*8 + q;
            float4 gt = *(float4*)&sG[b*520 + 4*hh];
            float ig = sigf(gt.x + p[q].x);
            float fg = sigf(gt.y + p[q].y);
            float cg = tanhfast(gt.z + p[q].z);
            float og = sigf(gt.w + p[q].w);
            c[q] = fmaf(fg, c[q], ig*cg);
            float h = og * tanhfast(c[q]);
            ((__nv_bfloat16*)sA)[(b*132 + hw)*2 + hb_byte] = __float2bfloat16(h);
            if (s == T_SZ-1) g_hn[2+dir][(b0+b)*128 + hh] = h;
        }
        __syncthreads();
    }
}

// ---------------- FC head ----------------
__global__ void __launch_bounds__(256) k_fc(const int* __restrict__ node_data,
                                            const float* __restrict__ emb,
                                            const float* __restrict__ fc1_b,
                                            const float* __restrict__ fc2_b)
{
    const int r = blockIdx.x;
    const int c = threadIdx.x;
    __shared__ float sh_in[256];
    __shared__ float sh_mid[256];

    int d = r >> 10;
    int b = ((r & 1023) << 1) + (c >> 7);
    int k = c & 127;
    sh_in[c] = g_hn[d][b*128 + k] + g_hn[2+d][b*128 + k];
    __syncthreads();

    float acc = fc1_b[c];
    #pragma unroll 4
    for (int i=0;i<256;i++) acc = fmaf(sh_in[i], g_fc1_wT[i*256 + c], acc);
    sh_mid[c] = sigf(acc);
    __syncthreads();

    if (c < 64){
        float a2 = fc2_b[c];
        #pragma unroll 4
        for (int i=0;i<256;i++) a2 = fmaf(sh_mid[i], g_fc2_wT[i*64 + c], a2);
        g_hidden[r*128 + c] = sigf(a2);
    } else if (c < 128){
        int e = c - 64;
        int n0 = node_data[r*2], n1 = node_data[r*2+1];
        g_hidden[r*128 + 64 + e] = 0.5f*(emb[n0*64 + e] + emb[n1*64 + e]);
    }
}

// ---------------- decoder: tensor-core GRU scans (unchanged, proven) ----------------
__global__ void __launch_bounds__(256) k_dec(const float* __restrict__ edge,
                                             const float* __restrict__ g2_bih,
                                             const float* __restrict__ g2_bhh,
                                             const float* __restrict__ dec_w,
                                             const float* __restrict__ dec_b,
                                             float* __restrict__ out)
{
    extern __shared__ char smem[];
    uint32_t* sA  = (uint32_t*)smem;               // [16][196]
    float*    sG  = (float*)(smem + 12544);        // [16][520]
    float*    sGB = (float*)(smem + 45824);        // [16][200]
    float*    h2s = (float*)(smem + 58624);        // [16][52]
    float*    res = (float*)(smem + 61952);        // [16]
    float*    dw  = (float*)(smem + 62016);        // [52]

    const int b0  = blockIdx.x * 16;
    const int tid = threadIdx.x;
    const int wid = tid >> 5, lane = tid & 31;
    const int g   = lane >> 2, tg = lane & 3;
    const int hh  = tid & 127, half = tid >> 7;
    const int n2  = tid & 63;
    const int half2 = (tid >> 6) & 1;
    const bool c_act = (tid < 128) && (n2 < 50);

    for (int i=tid; i<16*196; i+=256) sA[i] = 0u;
    if (tid < 52) dw[tid] = (tid < 50) ? dec_w[tid] : 0.0f;
    if (tid < 16) res[tid] = edge[(b0+tid)*T_SZ + (T_SZ-1)];
    __syncthreads();

    float h1[8];
    #pragma unroll
    for (int q=0;q<8;q++){
        int b = half*8 + q;
        h1[q] = g_hidden[(b0+b)*128 + hh];
        sA[b*196 + hh] = f2tf32(h1[q]);
    }
    float h2[8];
    #pragma unroll
    for (int q=0;q<8;q++) h2[q] = 0.0f;
    if (c_act){
        #pragma unroll
        for (int q=0;q<8;q++) h2s[(half2*8+q)*52 + n2] = 0.0f;
    }

    const float4 wi = ((const float4*)g_g1_wih)[hh];
    const float4 bi = ((const float4*)g_g1_bih)[hh];
    const float4 bh = ((const float4*)g_g1_bhh)[hh];
    float bBr=0.f, bBz=0.f, bBi=0.f, bBh=0.f;
    if (c_act){
        bBr = g2_bih[n2]     + g2_bhh[n2];
        bBz = g2_bih[50+n2]  + g2_bhh[50+n2];
        bBi = g2_bih[100+n2];
        bBh = g2_bhh[100+n2];
    }
    const float decb = dec_b[0];
    const u64* __restrict__ WF1 = (const u64*)g_g1F;
    const u64* __restrict__ WF2 = (const u64*)g_g2F;
    __syncthreads();

    for (int t=0; t<T_SZ; t++){
        float acc[8][4];
        #pragma unroll
        for (int j=0;j<8;j++)
            #pragma unroll
            for (int q=0;q<4;q++) acc[j][q] = 0.0f;
        #pragma unroll
        for (int kt=0;kt<16;kt++){
            uint32_t a0 = sA[g*196     + kt*8 + tg];
            uint32_t a1 = sA[(g+8)*196 + kt*8 + tg];
            uint32_t a2 = sA[g*196     + kt*8 + tg + 4];
            uint32_t a3 = sA[(g+8)*196 + kt*8 + tg + 4];
            #pragma unroll
            for (int j=0;j<8;j++){
                u64 wv = WF1[((wid*16 + kt)*8 + j)*32 + lane];
                uint32_t bw0 = (uint32_t)wv, bw1 = (uint32_t)(wv>>32);
                asm("mma.sync.aligned.m16n8k8.row.col.f32.tf32.tf32.f32 "
                    "{%0,%1,%2,%3}, {%4,%5,%6,%7}, {%8,%9}, {%0,%1,%2,%3};"
                    : "+f"(acc[j][0]), "+f"(acc[j][1]), "+f"(acc[j][2]), "+f"(acc[j][3])
                    : "r"(a0), "r"(a1), "r"(a2), "r"(a3), "r"(bw0), "r"(bw1));
            }
        }
        #pragma unroll
        for (int j=0;j<8;j++){
            int colb = wid*64 + j*8 + 2*tg;
            *(float2*)&sG[g*520 + colb]     = make_float2(acc[j][0], acc[j][1]);
            *(float2*)&sG[(g+8)*520 + colb] = make_float2(acc[j][2], acc[j][3]);
        }
        __syncthreads();

        #pragma unroll
        for (int q=0;q<8;q++){
            int b = half*8 + q;
            float4 gt = *(float4*)&sG[b*520 + 4*hh];
            float rv = res[b];
            float rg = sigf( fmaf(wi.x, rv, bi.x) + gt.x + bh.x );
            float zg = sigf( fmaf(wi.y, rv, bi.y) + gt.y + bh.y );
            float ng = tanhfast( fmaf(wi.z, rv, bi.z) + rg*(gt.z + bh.z) );
            h1[q] = fmaf(zg, h1[q] - ng, ng);
            sA[b*196 + hh] = f2tf32(h1[q]);
        }
        __syncthreads();

        if (wid < 4){
            float ac2[8][4];
            #pragma unroll
            for (int j=0;j<8;j++)
                #pragma unroll
                for (int q=0;q<4;q++) ac2[j][q] = 0.0f;
            #pragma unroll
            for (int kt=0;kt<24;kt++){
                uint32_t a0 = sA[g*196     + kt*8 + tg];
                uint32_t a1 = sA[(g+8)*196 + kt*8 + tg];
                uint32_t a2 = sA[g*196     + kt*8 + tg + 4];
                uint32_t a3 = sA[(g+8)*196 + kt*8 + tg + 4];
                #pragma unroll
                for (int j=0;j<8;j++){
                    u64 wv = WF2[((wid*24 + kt)*8 + j)*32 + lane];
                    uint32_t bw0 = (uint32_t)wv, bw1 = (uint32_t)(wv>>32);
                    asm("mma.sync.aligned.m16n8k8.row.col.f32.tf32.tf32.f32 "
                        "{%0,%1,%2,%3}, {%4,%5,%6,%7}, {%8,%9}, {%0,%1,%2,%3};"
                        : "+f"(ac2[j][0]), "+f"(ac2[j][1]), "+f"(ac2[j][2]), "+f"(ac2[j][3])
                        : "r"(a0), "r"(a1), "r"(a2), "r"(a3), "r"(bw0), "r"(bw1));
                }
            }
            #pragma unroll
            for (int j=0;j<8;j++){
                int colb = wid*64 + j*8 + 2*tg;
                *(float2*)&sGB[g*200 + colb]     = make_float2(ac2[j][0], ac2[j][1]);
                *(float2*)&sGB[(g+8)*200 + colb] = make_float2(ac2[j][2], ac2[j][3]);
            }
        }
        __syncthreads();

        if (c_act){
            #pragma unroll
            for (int q=0;q<8;q++){
                int b = half2*8 + q;
                float r2 = sigf(sGB[b*200 + n2]      + bBr);
                float z2 = sigf(sGB[b*200 + 50 + n2] + bBz);
                float nn = tanhfast( (sGB[b*200 + 100 + n2] + bBi) + r2*(sGB[b*200 + 150 + n2] + bBh) );
                h2[q] = fmaf(z2, h2[q] - nn, nn);
                sA[b*196 + 128 + n2] = f2tf32(h2[q]);
                h2s[b*52 + n2] = h2[q];
            }
        }
        __syncthreads();

        if (tid < 16){
            float s = decb;
            #pragma unroll 2
            for (int k=0;k<50;k++) s = fmaf(h2s[tid*52 + k], dw[k], s);
            float r = sigf(s);
            res[tid] = r;
            out[(b0+tid)*T_SZ + t] = r;
        }
        __syncthreads();
    }
}

extern "C" void kernel_launch(void* const* d_in, const int* in_sizes, int n_in,
                              void* d_out, int out_size)
{
    const int*   node_data = (const int*)  d_in[0];
    const float* edge_data = (const float*)d_in[1];
    const float* emb       = (const float*)d_in[2];
    const float* l1_wih_f  = (const float*)d_in[3];
    const float* l1_whh_f  = (const float*)d_in[4];
    const float* l1_b_f    = (const float*)d_in[5];
    const float* l1_wih_b  = (const float*)d_in[6];
    const float* l1_whh_b  = (const float*)d_in[7];
    const float* l1_b_b    = (const float*)d_in[8];
    const float* l2_wih_f  = (const float*)d_in[9];
    const float* l2_whh_f  = (const float*)d_in[10];
    const float* l2_b_f    = (const float*)d_in[11];
    const float* l2_wih_b  = (const float*)d_in[12];
    const float* l2_whh_b  = (const float*)d_in[13];
    const float* l2_b_b    = (const float*)d_in[14];
    const float* fc1_w     = (const float*)d_in[15];
    const float* fc1_b     = (const float*)d_in[16];
    const float* fc2_w     = (const float*)d_in[17];
    const float* fc2_b     = (const float*)d_in[18];
    const float* g1_wih    = (const float*)d_in[19];
    const float* g1_whh    = (const float*)d_in[20];
    const float* g1_bih    = (const float*)d_in[21];
    const float* g1_bhh    = (const float*)d_in[22];
    const float* g2_wih    = (const float*)d_in[23];
    const float* g2_whh    = (const float*)d_in[24];
    const float* g2_bih    = (const float*)d_in[25];
    const float* g2_bhh    = (const float*)d_in[26];
    const float* dec_w     = (const float*)d_in[27];
    const float* dec_b     = (const float*)d_in[28];
    float* out = (float*)d_out;

    cudaFuncSetAttribute(k_lstm1, cudaFuncAttributeMaxDynamicSharedMemorySize, 54528);
    cudaFuncSetAttribute(k_lstm2, cudaFuncAttributeMaxDynamicSharedMemorySize, 41728);
    cudaFuncSetAttribute(k_dec,   cudaFuncAttributeMaxDynamicSharedMemorySize, 62464);

    k_prep<<<256, 256>>>(l1_wih_f, l1_whh_f, l1_b_f, l1_wih_b, l1_whh_b, l1_b_b,
                         l2_wih_f, l2_whh_f, l2_b_f, l2_wih_b, l2_whh_b, l2_b_b,
                         fc1_w, fc2_w, g1_wih, g1_whh, g1_bih, g1_bhh,
                         g2_wih, g2_whh);
    k_lstm1<<<dim3(B_SZ/16, 2), 256, 54528>>>(edge_data);
    k_proj<<<dim3(((T_SZ*B_SZ)/128)*4, 1, 2), 256>>>();
    k_lstm2<<<dim3(B_SZ/16, 2), 256, 41728>>>();
    k_fc<<<B_SZ, 256>>>(node_data, emb, fc1_b, fc2_b);
    k_dec<<<B_SZ/16, 256, 62464>>>(edge_data, g2_bih, g2_bhh, dec_w, dec_b, out);
}